// round 8
// baseline (speedup 1.0000x reference)
#include <cuda_runtime.h>

// ---------------- constants ----------------
#define H      256      // hidden
#define TXT    768
#define BIO    32
#define TM     64       // rows per CTA
#define NTHR   256
#define EPSLN  1e-5f
#define PR     8        // rows per CTA in precompute kernels

typedef unsigned long long u64;

// ---------------- device scratch (precomputed folded weights) ----------------
__device__ float g_M [H * H];   // out_w @ Wv
__device__ float g_c [H];       // out_w @ bv + out_b
__device__ float g_Ag[H * H];   // (W1L @ M) * ln_text_g (column scaled)
__device__ float g_Bg[H * H];   // (W1R @ M) * ln_bio_g
__device__ float g_uA[H];       // (W1L@M) @ ln_text_g
__device__ float g_uB[H];       // (W1R@M) @ ln_bio_g
__device__ float g_e [H];       // (W1L@M)@ln_text_b + (W1R@M)@ln_bio_b + (W1L+W1R)@c + cls1_b

// ---------------- packed f32x2 helpers ----------------
__device__ __forceinline__ u64 pack_dup(float x) {
    u64 r; unsigned xi = __float_as_uint(x);
    asm("mov.b64 %0, {%1, %1};" : "=l"(r) : "r"(xi));
    return r;
}
__device__ __forceinline__ void ffma2(u64& d, u64 a, u64 b) {
    asm("fma.rn.f32x2 %0, %1, %2, %0;" : "+l"(d) : "l"(a), "l"(b));
}
__device__ __forceinline__ void unpack2(u64 v, float& lo, float& hi) {
    unsigned a, b;
    asm("mov.b64 {%0, %1}, %2;" : "=r"(a), "=r"(b) : "l"(v));
    lo = __uint_as_float(a); hi = __uint_as_float(b);
}

// ---------------- precompute 1: M = out_w @ Wv ; c = out_w @ bv + out_b ----------------
// 8 rows per CTA -> Wv streamed once per 8 output rows (8MB L2 total)
__global__ void precompute1(const float* __restrict__ in_proj_w,
                            const float* __restrict__ in_proj_b,
                            const float* __restrict__ out_w,
                            const float* __restrict__ out_b) {
    __shared__ float s_row[PR][H];
    __shared__ float s_part[8][PR];
    const int i0 = blockIdx.x * PR;
    const int j  = threadIdx.x;
    const int lane = j & 31, wrp = j >> 5;

#pragma unroll
    for (int r = 0; r < PR; r++) s_row[r][j] = out_w[(i0 + r) * H + j];
    __syncthreads();

    float acc[PR];
#pragma unroll
    for (int r = 0; r < PR; r++) acc[r] = 0.f;
#pragma unroll 4
    for (int k = 0; k < H; k++) {
        float w = in_proj_w[(2 * H + k) * H + j];
#pragma unroll
        for (int r = 0; r < PR; r++) acc[r] = fmaf(s_row[r][k], w, acc[r]);
    }
#pragma unroll
    for (int r = 0; r < PR; r++) g_M[(i0 + r) * H + j] = acc[r];

    // c[i] = dot(out_w[i], bv) + out_b[i]
    float bv = in_proj_b[2 * H + j];
    float cv[PR];
#pragma unroll
    for (int r = 0; r < PR; r++) {
        float v = s_row[r][j] * bv;
#pragma unroll
        for (int off = 16; off; off >>= 1) v += __shfl_xor_sync(0xffffffffu, v, off);
        cv[r] = v;
    }
    if (lane == 0)
#pragma unroll
        for (int r = 0; r < PR; r++) s_part[wrp][r] = cv[r];
    __syncthreads();
    if (j < PR) {
        float s = 0.f;
#pragma unroll
        for (int w = 0; w < 8; w++) s += s_part[w][j];
        g_c[i0 + j] = s + out_b[i0 + j];
    }
}

// ---------------- precompute 2: Ag, Bg, uA, uB, e (8 rows per CTA) ----------------
__global__ void precompute2(const float* __restrict__ cls1_w,
                            const float* __restrict__ cls1_b,
                            const float* __restrict__ ln_text_g,
                            const float* __restrict__ ln_text_b,
                            const float* __restrict__ ln_bio_g,
                            const float* __restrict__ ln_bio_b) {
    __shared__ float s_l[PR][H], s_r[PR][H];
    __shared__ float s_part[8][3 * PR];
    const int i0 = blockIdx.x * PR;
    const int j  = threadIdx.x;
    const int lane = j & 31, wrp = j >> 5;

#pragma unroll
    for (int r = 0; r < PR; r++) {
        s_l[r][j] = cls1_w[(i0 + r) * 2 * H + j];
        s_r[r][j] = cls1_w[(i0 + r) * 2 * H + H + j];
    }
    __syncthreads();

    float a[PR], b[PR];
#pragma unroll
    for (int r = 0; r < PR; r++) { a[r] = 0.f; b[r] = 0.f; }
#pragma unroll 4
    for (int k = 0; k < H; k++) {
        float m = g_M[k * H + j];
#pragma unroll
        for (int r = 0; r < PR; r++) {
            a[r] = fmaf(s_l[r][k], m, a[r]);
            b[r] = fmaf(s_r[r][k], m, b[r]);
        }
    }
    float gt = ln_text_g[j], gb = ln_bio_g[j];
    float lt = ln_text_b[j], lb = ln_bio_b[j];
    float cc = g_c[j];

    float vals[3 * PR];
#pragma unroll
    for (int r = 0; r < PR; r++) {
        float ag = a[r] * gt, bg = b[r] * gb;
        g_Ag[(i0 + r) * H + j] = ag;
        g_Bg[(i0 + r) * H + j] = bg;
        vals[r]          = ag;
        vals[PR + r]     = bg;
        vals[2 * PR + r] = a[r] * lt + b[r] * lb + (s_l[r][j] + s_r[r][j]) * cc;
    }
#pragma unroll
    for (int q = 0; q < 3 * PR; q++) {
        float v = vals[q];
#pragma unroll
        for (int off = 16; off; off >>= 1) v += __shfl_xor_sync(0xffffffffu, v, off);
        vals[q] = v;
    }
    if (lane == 0)
#pragma unroll
        for (int q = 0; q < 3 * PR; q++) s_part[wrp][q] = vals[q];
    __syncthreads();
    if (j < 3 * PR) {
        float s = 0.f;
#pragma unroll
        for (int w = 0; w < 8; w++) s += s_part[w][j];
        int q = j / PR, r = j % PR;
        if (q == 0) g_uA[i0 + r] = s;
        else if (q == 1) g_uB[i0 + r] = s;
        else g_e[i0 + r] = s + cls1_b[i0 + r];
    }
}

// ---------------- main fused kernel ----------------
__device__ __forceinline__ void load8(float* d, const float* p) {
    float4 v0 = *(const float4*)p;
    float4 v1 = *(const float4*)(p + 4);
    d[0] = v0.x; d[1] = v0.y; d[2] = v0.z; d[3] = v0.w;
    d[4] = v1.x; d[5] = v1.y; d[6] = v1.z; d[7] = v1.w;
}
__device__ __forceinline__ void loadB4(u64* b, const float* p) {
    ulonglong2 q0 = *(const ulonglong2*)p;
    ulonglong2 q1 = *(const ulonglong2*)(p + 4);
    b[0] = q0.x; b[1] = q0.y; b[2] = q1.x; b[3] = q1.y;
}

// smem floats: sX 32768 | s_w 8192 | s_a 2048 | vectors 2432  => 45440 floats
#define SMEM_FLOATS 45440
#define SMEM_BYTES  (SMEM_FLOATS * 4)

__global__ __launch_bounds__(NTHR, 1)
void fused_main(const float* __restrict__ bio,
                const float* __restrict__ text,
                const float* __restrict__ bio_w,
                const float* __restrict__ bio_b,
                const float* __restrict__ text_w,
                const float* __restrict__ text_b,
                const float* __restrict__ cls_ln_g,
                const float* __restrict__ cls_ln_b,
                const float* __restrict__ cls2_w,
                const float* __restrict__ cls2_b,
                float* __restrict__ out) {
    extern __shared__ float sm[];
    float* sX   = sm;                  // [64][512] : cols 0..255 = scaled x_t, 256..511 = scaled x_b
    float* s_w  = sX  + TM * 512;      // [32][256] staging (weights)
    float* s_a  = s_w + 32 * H;        // [32][64]  staging (activations, k-major)
    float* s_uA = s_a + 32 * TM;       // 256
    float* s_uB = s_uA + H;            // 256
    float* s_e  = s_uB + H;            // 256
    float* s_cg = s_e  + H;            // 256 cls_ln_g
    float* s_cb = s_cg + H;            // 256 cls_ln_b
    float* s_c2 = s_cb + H;            // 512 cls2_w
    float* s_tb = s_c2 + 2 * H;        // 256 text_b
    float* s_bb = s_tb + H;            // 256 bio_b
    float* s_at = s_bb + H;            // 64 alpha_text = -inv_t * m_t
    float* s_ab = s_at + TM;           // 64 alpha_bio

    const int tid = threadIdx.x;
    const int rg  = tid >> 5;          // warp id = row group (0..7)
    const int cg  = tid & 31;          // lane    = col group (0..31)
    const int R0  = rg * 8;
    const int C0  = cg * 8;
    const int row0 = blockIdx.x * TM;

    const float c2b0 = cls2_b[0];
    const float c2b1 = cls2_b[1];

    // ---- phase 0: stage small vectors + bio operands ----
    s_uA[tid] = g_uA[tid];
    s_uB[tid] = g_uB[tid];
    s_e [tid] = g_e [tid];
    s_cg[tid] = cls_ln_g[tid];
    s_cb[tid] = cls_ln_b[tid];
    s_c2[tid]       = cls2_w[tid];
    s_c2[H + tid]   = cls2_w[H + tid];
    s_tb[tid] = text_b[tid];
    s_bb[tid] = bio_b[tid];
    // bio_w [256][32] -> s_w[k][c]
    for (int idx = tid; idx < BIO * H; idx += NTHR) {
        int c = idx >> 5, k = idx & 31;
        s_w[k * H + c] = bio_w[idx];
    }
    // bio tile [64][32] -> s_a[k][r]
    for (int idx = tid; idx < TM * BIO; idx += NTHR) {
        int r = idx >> 5, k = idx & 31;
        s_a[k * TM + r] = bio[(row0 + r) * BIO + k];
    }
    __syncthreads();

    u64   acc2[8][4];
    float acc [8][8];

    // ---- phase 1: bio GEMM  X_b[64][256] = bio @ bio_w^T + bio_b ----
#pragma unroll
    for (int i = 0; i < 8; i++)
#pragma unroll
        for (int j = 0; j < 4; j++) acc2[i][j] = 0ull;

#pragma unroll 8
    for (int k = 0; k < BIO; k++) {
        float av[8]; u64 bv[4];
        load8(av, &s_a[k * TM + R0]);
        loadB4(bv, &s_w[k * H + C0]);
#pragma unroll
        for (int i = 0; i < 8; i++) {
            u64 aa = pack_dup(av[i]);
#pragma unroll
            for (int j = 0; j < 4; j++) ffma2(acc2[i][j], aa, bv[j]);
        }
    }
#pragma unroll
    for (int i = 0; i < 8; i++)
#pragma unroll
        for (int j = 0; j < 4; j++) {
            unpack2(acc2[i][j], acc[i][2 * j], acc[i][2 * j + 1]);
            acc[i][2 * j]     += s_bb[C0 + 2 * j];
            acc[i][2 * j + 1] += s_bb[C0 + 2 * j + 1];
        }

    // LN stats per row (warp owns rows R0..R0+7), store scaled to sX cols 256..511
#pragma unroll
    for (int i = 0; i < 8; i++) {
        float s = 0.f, q = 0.f;
#pragma unroll
        for (int j = 0; j < 8; j++) { float v = acc[i][j]; s += v; q = fmaf(v, v, q); }
#pragma unroll
        for (int off = 16; off; off >>= 1) {
            s += __shfl_xor_sync(0xffffffffu, s, off);
            q += __shfl_xor_sync(0xffffffffu, q, off);
        }
        float m   = s * (1.f / H);
        float inv = rsqrtf(fmaf(q, 1.f / H, -m * m) + EPSLN);
        if (cg == 0) s_ab[R0 + i] = -inv * m;
        float4 v0 = make_float4(acc[i][0]*inv, acc[i][1]*inv, acc[i][2]*inv, acc[i][3]*inv);
        float4 v1 = make_float4(acc[i][4]*inv, acc[i][5]*inv, acc[i][6]*inv, acc[i][7]*inv);
        *(float4*)&sX[(R0 + i) * 512 + 256 + C0]     = v0;
        *(float4*)&sX[(R0 + i) * 512 + 256 + C0 + 4] = v1;
    }
    __syncthreads();

    // ---- phase 2: text GEMM  X_t[64][256] = text @ text_w^T + text_b ----
#pragma unroll
    for (int i = 0; i < 8; i++)
#pragma unroll
        for (int j = 0; j < 4; j++) acc2[i][j] = 0ull;

    for (int kt = 0; kt < TXT / 32; kt++) {
        const int k0 = kt * 32;
        // stage text tile -> s_a[k][r]  (2048 floats, 512 float4)
#pragma unroll
        for (int u = 0; u < 2; u++) {
            int qd = tid + u * NTHR;           // 0..511
            int r  = qd >> 3;                  // 0..63
            int kq = qd & 7;                   // float4 index within 32 k
            float4 v = *(const float4*)&text[(row0 + r) * TXT + k0 + kq * 4];
            s_a[(kq * 4 + 0) * TM + r] = v.x;
            s_a[(kq * 4 + 1) * TM + r] = v.y;
            s_a[(kq * 4 + 2) * TM + r] = v.z;
            s_a[(kq * 4 + 3) * TM + r] = v.w;
        }
        // stage text_w tile -> s_w[k][c] (thread = output channel, 32B contiguous read)
        {
            const float4* src = (const float4*)&text_w[tid * TXT + k0];
#pragma unroll
            for (int u = 0; u < 8; u++) {
                float4 v = src[u];
                s_w[(u * 4 + 0) * H + tid] = v.x;
                s_w[(u * 4 + 1) * H + tid] = v.y;
                s_w[(u * 4 + 2) * H + tid] = v.z;
                s_w[(u * 4 + 3) * H + tid] = v.w;
            }
        }
        __syncthreads();
#pragma unroll 8
        for (int k = 0; k < 32; k++) {
            float av[8]; u64 bv[4];
            load8(av, &s_a[k * TM + R0]);
            loadB4(bv, &s_w[k * H + C0]);
#pragma unroll
            for (int i = 0; i < 8; i++) {
                u64 aa = pack_dup(av[i]);
#pragma unroll
                for (int j = 0; j < 4; j++) ffma2(acc2[i][j], aa, bv[j]);
            }
        }
        __syncthreads();
    }
#pragma unroll
    for (int i = 0; i < 8; i++)
#pragma unroll
        for (int j = 0; j < 4; j++) {
            unpack2(acc2[i][j], acc[i][2 * j], acc[i][2 * j + 1]);
            acc[i][2 * j]     += s_tb[C0 + 2 * j];
            acc[i][2 * j + 1] += s_tb[C0 + 2 * j + 1];
        }

    // LN stats, store scaled to sX cols 0..255
#pragma unroll
    for (int i = 0; i < 8; i++) {
        float s = 0.f, q = 0.f;
#pragma unroll
        for (int j = 0; j < 8; j++) { float v = acc[i][j]; s += v; q = fmaf(v, v, q); }
#pragma unroll
        for (int off = 16; off; off >>= 1) {
            s += __shfl_xor_sync(0xffffffffu, s, off);
            q += __shfl_xor_sync(0xffffffffu, q, off);
        }
        float m   = s * (1.f / H);
        float inv = rsqrtf(fmaf(q, 1.f / H, -m * m) + EPSLN);
        if (cg == 0) s_at[R0 + i] = -inv * m;
        float4 v0 = make_float4(acc[i][0]*inv, acc[i][1]*inv, acc[i][2]*inv, acc[i][3]*inv);
        float4 v1 = make_float4(acc[i][4]*inv, acc[i][5]*inv, acc[i][6]*inv, acc[i][7]*inv);
        *(float4*)&sX[(R0 + i) * 512 + C0]     = v0;
        *(float4*)&sX[(R0 + i) * 512 + C0 + 4] = v1;
    }
    __syncthreads();

    // ---- phase 3: Y[64][256] = sX(0:256) @ Ag^T + sX(256:512) @ Bg^T ----
#pragma unroll
    for (int i = 0; i < 8; i++)
#pragma unroll
        for (int j = 0; j < 4; j++) acc2[i][j] = 0ull;

    for (int kt = 0; kt < 16; kt++) {
        const int kc = kt * 32;
        // stage weight tile: s_w[kk][i] = W[i][kc+kk] (W = Ag for kc<256 else Bg)
        {
            const float* base = (kc < 256) ? (g_Ag + tid * H + kc)
                                           : (g_Bg + tid * H + (kc - 256));
            const float4* src = (const float4*)base;
#pragma unroll
            for (int u = 0; u < 8; u++) {
                float4 v = src[u];
                s_w[(u * 4 + 0) * H + tid] = v.x;
                s_w[(u * 4 + 1) * H + tid] = v.y;
                s_w[(u * 4 + 2) * H + tid] = v.z;
                s_w[(u * 4 + 3) * H + tid] = v.w;
            }
        }
        __syncthreads();
#pragma unroll 8
        for (int k = 0; k < 32; k++) {
            const int c = kc + k;
            u64 bv[4];
            loadB4(bv, &s_w[k * H + C0]);
#pragma unroll
            for (int i = 0; i < 8; i++) {
                u64 aa = pack_dup(sX[(R0 + i) * 512 + c]);   // warp-broadcast LDS
#pragma unroll
                for (int j = 0; j < 4; j++) ffma2(acc2[i][j], aa, bv[j]);
            }
        }
        __syncthreads();
    }
#pragma unroll
    for (int i = 0; i < 8; i++)
#pragma unroll
        for (int j = 0; j < 4; j++)
            unpack2(acc2[i][j], acc[i][2 * j], acc[i][2 * j + 1]);

    // rank-1 LN-mean corrections + fused constant
    {
        float uA[8], uB[8], ee[8];
        load8(uA, &s_uA[C0]);
        load8(uB, &s_uB[C0]);
        load8(ee, &s_e [C0]);
#pragma unroll
        for (int i = 0; i < 8; i++) {
            float at = s_at[R0 + i];
            float ab = s_ab[R0 + i];
#pragma unroll
            for (int j = 0; j < 8; j++)
                acc[i][j] = fmaf(at, uA[j], fmaf(ab, uB[j], acc[i][j] + ee[j]));
        }
    }

    // ---- phase 4: final LN + ReLU + 2-way head ----
    float cgv[8], cbv[8], w0v[8], w1v[8];
    load8(cgv, &s_cg[C0]);
    load8(cbv, &s_cb[C0]);
    load8(w0v, &s_c2[C0]);
    load8(w1v, &s_c2[H + C0]);

#pragma unroll
    for (int i = 0; i < 8; i++) {
        float s = 0.f, q = 0.f;
#pragma unroll
        for (int j = 0; j < 8; j++) { float v = acc[i][j]; s += v; q = fmaf(v, v, q); }
#pragma unroll
        for (int off = 16; off; off >>= 1) {
            s += __shfl_xor_sync(0xffffffffu, s, off);
            q += __shfl_xor_sync(0xffffffffu, q, off);
        }
        float m   = s * (1.f / H);
        float inv = rsqrtf(fmaf(q, 1.f / H, -m * m) + EPSLN);
        float p0 = 0.f, p1 = 0.f;
#pragma unroll
        for (int j = 0; j < 8; j++) {
            float h = fmaf((acc[i][j] - m) * inv, cgv[j], cbv[j]);
            h = fmaxf(h, 0.f);
            p0 = fmaf(h, w0v[j], p0);
            p1 = fmaf(h, w1v[j], p1);
        }
#pragma unroll
        for (int off = 16; off; off >>= 1) {
            p0 += __shfl_xor_sync(0xffffffffu, p0, off);
            p1 += __shfl_xor_sync(0xffffffffu, p1, off);
        }
        if (cg == 0) {
            int r = row0 + R0 + i;
            out[2 * r + 0] = p0 + c2b0;
            out[2 * r + 1] = p1 + c2b1;
        }
    }
}

// ---------------- launch ----------------
extern "C" void kernel_launch(void* const* d_in, const int* in_sizes, int n_in,
                              void* d_out, int out_size) {
    const float* bio       = (const float*)d_in[0];
    const float* text      = (const float*)d_in[1];
    const float* bio_w     = (const float*)d_in[2];
    const float* bio_b     = (const float*)d_in[3];
    const float* text_w    = (const float*)d_in[4];
    const float* text_b    = (const float*)d_in[5];
    const float* ln_bio_g  = (const float*)d_in[6];
    const float* ln_bio_b  = (const float*)d_in[7];
    const float* ln_text_g = (const float*)d_in[8];
    const float* ln_text_b = (const float*)d_in[9];
    const float* in_proj_w = (const float*)d_in[10];
    const float* in_proj_b = (const float*)d_in[11];
    const float* out_w     = (const float*)d_in[12];
    const float* out_b     = (const float*)d_in[13];
    const float* cls1_w    = (const float*)d_in[14];
    const float* cls1_b    = (const float*)d_in[15];
    const float* cls_ln_g  = (const float*)d_in[16];
    const float* cls_ln_b  = (const float*)d_in[17];
    const float* cls2_w    = (const float*)d_in[18];
    const float* cls2_b    = (const float*)d_in[19];
    float* out = (float*)d_out;

    const int B = in_sizes[0] / BIO;   // 65536

    precompute1<<<H / PR, NTHR>>>(in_proj_w, in_proj_b, out_w, out_b);
    precompute2<<<H / PR, NTHR>>>(cls1_w, cls1_b, ln_text_g, ln_text_b, ln_bio_g, ln_bio_b);

    cudaFuncSetAttribute(fused_main, cudaFuncAttributeMaxDynamicSharedMemorySize, SMEM_BYTES);
    fused_main<<<B / TM, NTHR, SMEM_BYTES>>>(bio, text, bio_w, bio_b,
                                             text_w, text_b,
                                             cls_ln_g, cls_ln_b,
                                             cls2_w, cls2_b, out);
}

// round 9
// speedup vs baseline: 2.1201x; 2.1201x over previous
#include <cuda_runtime.h>
#include <cuda_bf16.h>

#define H      256
#define TXT    768
#define BIO    32
#define TM     64
#define NTHR   256
#define EPSLN  1e-5f
#define PR     8

#define LDA3   520      // A3 smem pitch (bf16 elems): 512 + 8 pad
#define LDT    40       // K-tile smem pitch (bf16 elems): 32 + 8 pad

// ---------------- device scratch ----------------
__device__ float g_M [H * H];
__device__ float g_c [H];
__device__ float g_Ag[H * H];
__device__ float g_Bg[H * H];
__device__ float g_uA[H];
__device__ float g_uB[H];
__device__ float g_e [H];

__device__ __align__(16) __nv_bfloat16 g_W1h[H * BIO], g_W1l[H * BIO];   // [n][k]
__device__ __align__(16) __nv_bfloat16 g_W2h[H * TXT], g_W2l[H * TXT];   // [n][k]
__device__ __align__(16) __nv_bfloat16 g_W3h[H * 512], g_W3l[H * 512];   // [n][k]

// ---------------- precompute 1 ----------------
__global__ void precompute1(const float* __restrict__ in_proj_w,
                            const float* __restrict__ in_proj_b,
                            const float* __restrict__ out_w,
                            const float* __restrict__ out_b) {
    __shared__ float s_row[PR][H];
    __shared__ float s_part[8][PR];
    const int i0 = blockIdx.x * PR;
    const int j  = threadIdx.x;
    const int lane = j & 31, wrp = j >> 5;
#pragma unroll
    for (int r = 0; r < PR; r++) s_row[r][j] = out_w[(i0 + r) * H + j];
    __syncthreads();
    float acc[PR];
#pragma unroll
    for (int r = 0; r < PR; r++) acc[r] = 0.f;
#pragma unroll 4
    for (int k = 0; k < H; k++) {
        float w = in_proj_w[(2 * H + k) * H + j];
#pragma unroll
        for (int r = 0; r < PR; r++) acc[r] = fmaf(s_row[r][k], w, acc[r]);
    }
#pragma unroll
    for (int r = 0; r < PR; r++) g_M[(i0 + r) * H + j] = acc[r];
    float bv = in_proj_b[2 * H + j];
#pragma unroll
    for (int r = 0; r < PR; r++) {
        float v = s_row[r][j] * bv;
#pragma unroll
        for (int off = 16; off; off >>= 1) v += __shfl_xor_sync(0xffffffffu, v, off);
        if (lane == 0) s_part[wrp][r] = v;
    }
    __syncthreads();
    if (j < PR) {
        float s = 0.f;
#pragma unroll
        for (int w = 0; w < 8; w++) s += s_part[w][j];
        g_c[i0 + j] = s + out_b[i0 + j];
    }
}

// ---------------- precompute 2 ----------------
__global__ void precompute2(const float* __restrict__ cls1_w,
                            const float* __restrict__ cls1_b,
                            const float* __restrict__ ln_text_g,
                            const float* __restrict__ ln_text_b,
                            const float* __restrict__ ln_bio_g,
                            const float* __restrict__ ln_bio_b) {
    __shared__ float s_l[PR][H], s_r[PR][H];
    __shared__ float s_part[8][3 * PR];
    const int i0 = blockIdx.x * PR;
    const int j  = threadIdx.x;
    const int lane = j & 31, wrp = j >> 5;
#pragma unroll
    for (int r = 0; r < PR; r++) {
        s_l[r][j] = cls1_w[(i0 + r) * 2 * H + j];
        s_r[r][j] = cls1_w[(i0 + r) * 2 * H + H + j];
    }
    __syncthreads();
    float a[PR], b[PR];
#pragma unroll
    for (int r = 0; r < PR; r++) { a[r] = 0.f; b[r] = 0.f; }
#pragma unroll 4
    for (int k = 0; k < H; k++) {
        float m = g_M[k * H + j];
#pragma unroll
        for (int r = 0; r < PR; r++) {
            a[r] = fmaf(s_l[r][k], m, a[r]);
            b[r] = fmaf(s_r[r][k], m, b[r]);
        }
    }
    float gt = ln_text_g[j], gb = ln_bio_g[j];
    float lt = ln_text_b[j], lb = ln_bio_b[j];
    float cc = g_c[j];
    float vals[3 * PR];
#pragma unroll
    for (int r = 0; r < PR; r++) {
        float ag = a[r] * gt, bg = b[r] * gb;
        g_Ag[(i0 + r) * H + j] = ag;
        g_Bg[(i0 + r) * H + j] = bg;
        vals[r]          = ag;
        vals[PR + r]     = bg;
        vals[2 * PR + r] = a[r] * lt + b[r] * lb + (s_l[r][j] + s_r[r][j]) * cc;
    }
#pragma unroll
    for (int q = 0; q < 3 * PR; q++) {
        float v = vals[q];
#pragma unroll
        for (int off = 16; off; off >>= 1) v += __shfl_xor_sync(0xffffffffu, v, off);
        if (lane == 0) s_part[wrp][q] = v;
    }
    __syncthreads();
    if (j < 3 * PR) {
        float s = 0.f;
#pragma unroll
        for (int w = 0; w < 8; w++) s += s_part[w][j];
        int q = j / PR, r = j % PR;
        if (q == 0) g_uA[i0 + r] = s;
        else if (q == 1) g_uB[i0 + r] = s;
        else g_e[i0 + r] = s + cls1_b[i0 + r];
    }
}

// ---------------- precompute 3: bf16 hi/lo splits ----------------
__global__ void convert_weights(const float* __restrict__ bio_w,
                                const float* __restrict__ text_w) {
    int i = blockIdx.x * NTHR + threadIdx.x;
    if (i < H * BIO) {
        float v = bio_w[i];
        __nv_bfloat16 h = __float2bfloat16(v);
        g_W1h[i] = h;
        g_W1l[i] = __float2bfloat16(v - __bfloat162float(h));
    }
    if (i < H * 512) {
        int n = i >> 9, k = i & 511;
        float v = (k < H) ? g_Ag[n * H + k] : g_Bg[n * H + (k - H)];
        __nv_bfloat16 h = __float2bfloat16(v);
        g_W3h[i] = h;
        g_W3l[i] = __float2bfloat16(v - __bfloat162float(h));
    }
    if (i < H * TXT) {
        float v = text_w[i];
        __nv_bfloat16 h = __float2bfloat16(v);
        g_W2h[i] = h;
        g_W2l[i] = __float2bfloat16(v - __bfloat162float(h));
    }
}

// ---------------- mma helpers ----------------
__device__ __forceinline__ unsigned s2u(const void* p) {
    return (unsigned)__cvta_generic_to_shared(p);
}
__device__ __forceinline__ void ldsm4(unsigned* r, unsigned a) {
    asm volatile("ldmatrix.sync.aligned.m8n8.x4.shared.b16 {%0,%1,%2,%3}, [%4];"
                 : "=r"(r[0]), "=r"(r[1]), "=r"(r[2]), "=r"(r[3]) : "r"(a));
}
__device__ __forceinline__ void mma16816(float* d, const unsigned* a, const unsigned* b) {
    asm volatile("mma.sync.aligned.m16n8k16.row.col.f32.bf16.bf16.f32 "
                 "{%0,%1,%2,%3}, {%4,%5,%6,%7}, {%8,%9}, {%0,%1,%2,%3};"
                 : "+f"(d[0]), "+f"(d[1]), "+f"(d[2]), "+f"(d[3])
                 : "r"(a[0]), "r"(a[1]), "r"(a[2]), "r"(a[3]), "r"(b[0]), "r"(b[1]));
}
// one k16 step against 128 n-cols (8 ldsm4 pairs), 3-product hi/lo split
__device__ __forceinline__ void kstep(unsigned aH, unsigned aL,
                                      unsigned bH, unsigned bL,
                                      float (*acc)[4]) {
    unsigned ah[4], al[4];
    ldsm4(ah, aH);
    ldsm4(al, aL);
#pragma unroll
    for (int p = 0; p < 8; p++) {
        unsigned bh[4], bl[4];
        ldsm4(bh, bH + p * 16 * (LDT * 2));
        ldsm4(bl, bL + p * 16 * (LDT * 2));
        mma16816(acc[2 * p],     ah, bh);
        mma16816(acc[2 * p],     ah, bl);
        mma16816(acc[2 * p],     al, bh);
        mma16816(acc[2 * p + 1], ah, bh + 2);
        mma16816(acc[2 * p + 1], ah, bl + 2);
        mma16816(acc[2 * p + 1], al, bh + 2);
    }
}

// ---------------- smem layout (byte offsets) ----------------
#define OFF_A3H 0
#define OFF_A3L 66560
#define OFF_A2H 133120
#define OFF_A2L 138240
#define OFF_BH  143360
#define OFF_BL  163840
#define OFF_VEC 184320
#define OFF_SS  193536
#define OFF_SQ  194048
#define OFF_AT  194560
#define OFF_AB  194816
#define OFF_HD  195072
#define SMEM_BYTES 196096

// vec region float offsets
#define V_TB 0
#define V_BB 256
#define V_UA 512
#define V_UB 768
#define V_E  1024
#define V_CG 1280
#define V_CB 1536
#define V_C2 1792

// bias add + LN + hi/lo writeback of scaled activations into A3
__device__ __forceinline__ void ln_writeback(
    float (*acc)[4], const float* bias, float* statS, float* statQ,
    __nv_bfloat16* A3h, __nv_bfloat16* A3l, int colBase, float* alpha,
    int wm, int wn, int lane) {
    const int q = lane & 3, rq = lane >> 2;
    const int rlo = wm * 16 + rq, rhi = rlo + 8;
#pragma unroll
    for (int nt = 0; nt < 16; nt++) {
        int c = wn * 128 + nt * 8 + 2 * q;
        float b0 = bias[c], b1 = bias[c + 1];
        acc[nt][0] += b0; acc[nt][1] += b1;
        acc[nt][2] += b0; acc[nt][3] += b1;
    }
    float sl = 0.f, ql = 0.f, sh = 0.f, qh = 0.f;
#pragma unroll
    for (int nt = 0; nt < 16; nt++) {
        sl += acc[nt][0] + acc[nt][1];
        sh += acc[nt][2] + acc[nt][3];
        ql = fmaf(acc[nt][0], acc[nt][0], fmaf(acc[nt][1], acc[nt][1], ql));
        qh = fmaf(acc[nt][2], acc[nt][2], fmaf(acc[nt][3], acc[nt][3], qh));
    }
#pragma unroll
    for (int o = 1; o <= 2; o <<= 1) {
        sl += __shfl_xor_sync(0xffffffffu, sl, o);
        ql += __shfl_xor_sync(0xffffffffu, ql, o);
        sh += __shfl_xor_sync(0xffffffffu, sh, o);
        qh += __shfl_xor_sync(0xffffffffu, qh, o);
    }
    if (q == 0) {
        statS[wn * 64 + rlo] = sl; statQ[wn * 64 + rlo] = ql;
        statS[wn * 64 + rhi] = sh; statQ[wn * 64 + rhi] = qh;
    }
    __syncthreads();
    float Sl = statS[rlo] + statS[64 + rlo], Ql = statQ[rlo] + statQ[64 + rlo];
    float Sh = statS[rhi] + statS[64 + rhi], Qh = statQ[rhi] + statQ[64 + rhi];
    float ml = Sl * (1.f / H), il = rsqrtf(fmaf(Ql, 1.f / H, -ml * ml) + EPSLN);
    float mh = Sh * (1.f / H), ih = rsqrtf(fmaf(Qh, 1.f / H, -mh * mh) + EPSLN);
    if (q == 0 && wn == 0) { alpha[rlo] = -il * ml; alpha[rhi] = -ih * mh; }
#pragma unroll
    for (int nt = 0; nt < 16; nt++) {
        int c = colBase + wn * 128 + nt * 8 + 2 * q;
        float v; __nv_bfloat16 hh;
        v = acc[nt][0] * il; hh = __float2bfloat16(v);
        A3h[rlo * LDA3 + c] = hh;     A3l[rlo * LDA3 + c] = __float2bfloat16(v - __bfloat162float(hh));
        v = acc[nt][1] * il; hh = __float2bfloat16(v);
        A3h[rlo * LDA3 + c + 1] = hh; A3l[rlo * LDA3 + c + 1] = __float2bfloat16(v - __bfloat162float(hh));
        v = acc[nt][2] * ih; hh = __float2bfloat16(v);
        A3h[rhi * LDA3 + c] = hh;     A3l[rhi * LDA3 + c] = __float2bfloat16(v - __bfloat162float(hh));
        v = acc[nt][3] * ih; hh = __float2bfloat16(v);
        A3h[rhi * LDA3 + c + 1] = hh; A3l[rhi * LDA3 + c + 1] = __float2bfloat16(v - __bfloat162float(hh));
    }
}

// ---------------- main fused kernel ----------------
__global__ __launch_bounds__(NTHR, 1)
void fused_main(const float* __restrict__ bio,
                const float* __restrict__ text,
                const float* __restrict__ bio_b,
                const float* __restrict__ text_b,
                const float* __restrict__ cls_ln_g,
                const float* __restrict__ cls_ln_b,
                const float* __restrict__ cls2_w,
                const float* __restrict__ cls2_b,
                float* __restrict__ out) {
    extern __shared__ char sm[];
    __nv_bfloat16* A3h = (__nv_bfloat16*)(sm + OFF_A3H);
    __nv_bfloat16* A3l = (__nv_bfloat16*)(sm + OFF_A3L);
    __nv_bfloat16* A2h = (__nv_bfloat16*)(sm + OFF_A2H);
    __nv_bfloat16* A2l = (__nv_bfloat16*)(sm + OFF_A2L);
    __nv_bfloat16* Bh  = (__nv_bfloat16*)(sm + OFF_BH);
    __nv_bfloat16* Bl  = (__nv_bfloat16*)(sm + OFF_BL);
    float* vec   = (float*)(sm + OFF_VEC);
    float* statS = (float*)(sm + OFF_SS);
    float* statQ = (float*)(sm + OFF_SQ);
    float* s_at  = (float*)(sm + OFF_AT);
    float* s_ab  = (float*)(sm + OFF_AB);
    float* s_hd  = (float*)(sm + OFF_HD);

    const int tid  = threadIdx.x;
    const int lane = tid & 31, wid = tid >> 5;
    const int wm = wid >> 1, wn = wid & 1;
    const int row0 = blockIdx.x * TM;

    const int aRowL = lane & 15;
    const int aKoff = (lane >> 4) << 3;
    const int bNoff = ((lane >> 4) << 3) + (lane & 7);
    const int bKoff = ((lane >> 3) & 1) << 3;

    const float c2b0 = cls2_b[0];
    const float c2b1 = cls2_b[1];

    const unsigned uA3h = s2u(A3h), uA3l = s2u(A3l);
    const unsigned uA2h = s2u(A2h), uA2l = s2u(A2l);
    const unsigned uBh  = s2u(Bh),  uBl  = s2u(Bl);

    // ---- phase 0: stage vectors + bio activations (split) + W1 ----
    vec[V_TB + tid] = text_b[tid];
    vec[V_BB + tid] = bio_b[tid];
    vec[V_UA + tid] = g_uA[tid];
    vec[V_UB + tid] = g_uB[tid];
    vec[V_E  + tid] = g_e[tid];
    vec[V_CG + tid] = cls_ln_g[tid];
    vec[V_CB + tid] = cls_ln_b[tid];
    vec[V_C2 + tid]       = cls2_w[tid];
    vec[V_C2 + 256 + tid] = cls2_w[256 + tid];

#pragma unroll
    for (int u = 0; u < 2; u++) {                       // bio 64x32 fp32 -> A2 hi/lo
        int qd = tid + u * NTHR;                        // 0..511 float4s
        int r = qd >> 3, kq = qd & 7;
        float4 v = *(const float4*)&bio[(row0 + r) * BIO + kq * 4];
        float vv[4] = {v.x, v.y, v.z, v.w};
#pragma unroll
        for (int i = 0; i < 4; i++) {
            __nv_bfloat16 h = __float2bfloat16(vv[i]);
            A2h[r * LDT + kq * 4 + i] = h;
            A2l[r * LDT + kq * 4 + i] = __float2bfloat16(vv[i] - __bfloat162float(h));
        }
    }
#pragma unroll
    for (int u = 0; u < 4; u++) {                       // W1 256x32 bf16 hi/lo
        int qd = tid + u * NTHR;                        // 0..1023 uint4s
        int n = qd >> 2, c = qd & 3;
        *(uint4*)((char*)Bh + n * 80 + c * 16) = *(const uint4*)((const char*)g_W1h + n * 64 + c * 16);
        *(uint4*)((char*)Bl + n * 80 + c * 16) = *(const uint4*)((const char*)g_W1l + n * 64 + c * 16);
    }
    __syncthreads();

    float acc[16][4];

    // ---- phase 1: bio GEMM (K=32) ----
#pragma unroll
    for (int nt = 0; nt < 16; nt++)
#pragma unroll
        for (int j = 0; j < 4; j++) acc[nt][j] = 0.f;
#pragma unroll
    for (int ks = 0; ks < 32; ks += 16) {
        kstep(uA2h + 2 * ((wm * 16 + aRowL) * LDT + ks + aKoff),
              uA2l + 2 * ((wm * 16 + aRowL) * LDT + ks + aKoff),
              uBh  + 2 * ((wn * 128 + bNoff) * LDT + ks + bKoff),
              uBl  + 2 * ((wn * 128 + bNoff) * LDT + ks + bKoff), acc);
    }
    ln_writeback(acc, vec + V_BB, statS, statQ, A3h, A3l, 256, s_ab, wm, wn, lane);

    // ---- phase 2: text GEMM (K=768) ----
#pragma unroll
    for (int nt = 0; nt < 16; nt++)
#pragma unroll
        for (int j = 0; j < 4; j++) acc[nt][j] = 0.f;

    for (int kt = 0; kt < 24; kt++) {
        const int k0g = kt * 32;
        __syncthreads();                                 // prior reads done before restage
#pragma unroll
        for (int u = 0; u < 2; u++) {                    // text tile 64x32 fp32 -> hi/lo
            int qd = tid + u * NTHR;
            int r = qd >> 3, kq = qd & 7;
            float4 v = *(const float4*)&text[(row0 + r) * TXT + k0g + kq * 4];
            float vv[4] = {v.x, v.y, v.z, v.w};
#pragma unroll
            for (int i = 0; i < 4; i++) {
                __nv_bfloat16 h = __float2bfloat16(vv[i]);
                A2h[r * LDT + kq * 4 + i] = h;
                A2l[r * LDT + kq * 4 + i] = __float2bfloat16(vv[i] - __bfloat162float(h));
            }
        }
#pragma unroll
        for (int u = 0; u < 4; u++) {                    // W2 tile 256x32
            int qd = tid + u * NTHR;
            int n = qd >> 2, c = qd & 3;
            *(uint4*)((char*)Bh + n * 80 + c * 16) =
                *(const uint4*)((const char*)g_W2h + n * (TXT * 2) + k0g * 2 + c * 16);
            *(uint4*)((char*)Bl + n * 80 + c * 16) =
                *(const uint4*)((const char*)g_W2l + n * (TXT * 2) + k0g * 2 + c * 16);
        }
        __syncthreads();
#pragma unroll
        for (int ks = 0; ks < 32; ks += 16) {
            kstep(uA2h + 2 * ((wm * 16 + aRowL) * LDT + ks + aKoff),
                  uA2l + 2 * ((wm * 16 + aRowL) * LDT + ks + aKoff),
                  uBh  + 2 * ((wn * 128 + bNoff) * LDT + ks + bKoff),
                  uBl  + 2 * ((wn * 128 + bNoff) * LDT + ks + bKoff), acc);
        }
    }
    __syncthreads();
    ln_writeback(acc, vec + V_TB, statS, statQ, A3h, A3l, 0, s_at, wm, wn, lane);

    // ---- phase 3: classifier GEMM Y[64][256] = A3(64x512) @ W3^T ----
#pragma unroll
    for (int nt = 0; nt < 16; nt++)
#pragma unroll
        for (int j = 0; j < 4; j++) acc[nt][j] = 0.f;

    for (int kt = 0; kt < 16; kt++) {
        const int k0g = kt * 32;
        __syncthreads();
#pragma unroll
        for (int u = 0; u < 4; u++) {                    // W3 tile 256x32
            int qd = tid + u * NTHR;
            int n = qd >> 2, c = qd & 3;
            *(uint4*)((char*)Bh + n * 80 + c * 16) =
                *(const uint4*)((const char*)g_W3h + n * 1024 + k0g * 2 + c * 16);
            *(uint4*)((char*)Bl + n * 80 + c * 16) =
                *(const uint4*)((const char*)g_W3l + n * 1024 + k0g * 2 + c * 16);
        }
        __syncthreads();
#pragma unroll
        for (int ks = 0; ks < 32; ks += 16) {
            kstep(uA3h + 2 * ((wm * 16 + aRowL) * LDA3 + k0g + ks + aKoff),
                  uA3l + 2 * ((wm * 16 + aRowL) * LDA3 + k0g + ks + aKoff),
                  uBh  + 2 * ((wn * 128 + bNoff) * LDT + ks + bKoff),
                  uBl  + 2 * ((wn * 128 + bNoff) * LDT + ks + bKoff), acc);
        }
    }

    // ---- phase 4: rank-1 corrections, final LN + ReLU + head ----
    const int q = lane & 3, rq = lane >> 2;
    const int rlo = wm * 16 + rq, rhi = rlo + 8;
    {
        float atl = s_at[rlo], ath = s_at[rhi];
        float abl = s_ab[rlo], abh = s_ab[rhi];
#pragma unroll
        for (int nt = 0; nt < 16; nt++) {
            int c = wn * 128 + nt * 8 + 2 * q;
            float uA0 = vec[V_UA + c], uA1 = vec[V_UA + c + 1];
            float uB0 = vec[V_UB + c], uB1 = vec[V_UB + c + 1];
            float e0  = vec[V_E + c],  e1  = vec[V_E + c + 1];
            acc[nt][0] = fmaf(atl, uA0, fmaf(abl, uB0, acc[nt][0] + e0));
            acc[nt][1] = fmaf(atl, uA1, fmaf(abl, uB1, acc[nt][1] + e1));
            acc[nt][2] = fmaf(ath, uA0, fmaf(abh, uB0, acc[nt][2] + e0));
            acc[nt][3] = fmaf(ath, uA1, fmaf(abh, uB1, acc[nt][3] + e1));
        }
    }
    float sl = 0.f, ql = 0.f, sh = 0.f, qh = 0.f;
#pragma unroll
    for (int nt = 0; nt < 16; nt++) {
        sl += acc[nt][0] + acc[nt][1];
        sh += acc[nt][2] + acc[nt][3];
        ql = fmaf(acc[nt][0], acc[nt][0], fmaf(acc[nt][1], acc[nt][1], ql));
        qh = fmaf(acc[nt][2], acc[nt][2], fmaf(acc[nt][3], acc[nt][3], qh));
    }
#pragma unroll
    for (int o = 1; o <= 2; o <<= 1) {
        sl += __shfl_xor_sync(0xffffffffu, sl, o);
        ql += __shfl_xor_sync(0xffffffffu, ql, o);
        sh += __shfl_xor_sync(0xffffffffu, sh, o);
        qh += __shfl_xor_sync(0xffffffffu, qh, o);
    }
    __syncthreads();                                     // statS free to reuse
    if (q == 0) {
        statS[wn * 64 + rlo] = sl; statQ[wn * 64 + rlo] = ql;
        statS[wn * 64 + rhi] = sh; statQ[wn * 64 + rhi] = qh;
    }
    __syncthreads();
    float Sl = statS[rlo] + statS[64 + rlo], Ql = statQ[rlo] + statQ[64 + rlo];
    float Sh = statS[rhi] + statS[64 + rhi], Qh = statQ[rhi] + statQ[64 + rhi];
    float ml = Sl * (1.f / H), il = rsqrtf(fmaf(Ql, 1.f / H, -ml * ml) + EPSLN);
    float mh = Sh * (1.f / H), ih = rsqrtf(fmaf(Qh, 1.f / H, -mh * mh) + EPSLN);

    float p0l = 0.f, p1l = 0.f, p0h = 0.f, p1h = 0.f;
#pragma unroll
    for (int nt = 0; nt < 16; nt++) {
        int c = wn * 128 + nt * 8 + 2 * q;
#pragma unroll
        for (int d = 0; d < 2; d++) {
            float cg = vec[V_CG + c + d], cb = vec[V_CB + c + d];
            float w0 = vec[V_C2 + c + d], w1 = vec[V_C2 + 256 + c + d];
            float hv = fmaxf(fmaf((acc[nt][d]     - ml) * il, cg, cb), 0.f);
            p0l = fmaf(hv, w0, p0l); p1l = fmaf(hv, w1, p1l);
            hv = fmaxf(fmaf((acc[nt][2 + d] - mh) * ih, cg, cb), 0.f);
            p0h = fmaf(hv, w0, p0h); p1h = fmaf(hv, w1, p1h);
        }
    }
#pragma unroll
    for (int o = 1; o <= 2; o <<= 1) {
        p0l += __shfl_xor_sync(0xffffffffu, p0l, o);
        p1l += __shfl_xor_sync(0xffffffffu, p1l, o);
        p0h += __shfl_xor_sync(0xffffffffu, p0h, o);
        p1h += __shfl_xor_sync(0xffffffffu, p1h, o);
    }
    if (q == 0) {
        s_hd[wn * 128 + rlo * 2]     = p0l;
        s_hd[wn * 128 + rlo * 2 + 1] = p1l;
        s_hd[wn * 128 + rhi * 2]     = p0h;
        s_hd[wn * 128 + rhi * 2 + 1] = p1h;
    }
    __syncthreads();
    if (tid < TM) {
        int r = row0 + tid;
        out[2 * r]     = s_hd[tid * 2]     + s_hd[128 + tid * 2]     + c2b0;
        out[2 * r + 1] = s_hd[tid * 2 + 1] + s_hd[128 + tid * 2 + 1] + c2b1;
    }
}

// ---------------- launch ----------------
extern "C" void kernel_launch(void* const* d_in, const int* in_sizes, int n_in,
                              void* d_out, int out_size) {
    const float* bio       = (const float*)d_in[0];
    const float* text      = (const float*)d_in[1];
    const float* bio_w     = (const float*)d_in[2];
    const float* bio_b     = (const float*)d_in[3];
    const float* text_w    = (const float*)d_in[4];
    const float* text_b    = (const float*)d_in[5];
    const float* ln_bio_g  = (const float*)d_in[6];
    const float* ln_bio_b  = (const float*)d_in[7];
    const float* ln_text_g = (const float*)d_in[8];
    const float* ln_text_b = (const float*)d_in[9];
    const float* in_proj_w = (const float*)d_in[10];
    const float* in_proj_b = (const float*)d_in[11];
    const float* out_w     = (const float*)d_in[12];
    const float* out_b     = (const float*)d_in[13];
    const float* cls1_w    = (const float*)d_in[14];
    const float* cls1_b    = (const float*)d_in[15];
    const float* cls_ln_g  = (const float*)d_in[16];
    const float* cls_ln_b  = (const float*)d_in[17];
    const float* cls2_w    = (const float*)d_in[18];
    const float* cls2_b    = (const float*)d_in[19];
    float* out = (float*)d_out;

    const int B = in_sizes[0] / BIO;   // 65536

    precompute1<<<H / PR, NTHR>>>(in_proj_w, in_proj_b, out_w, out_b);
    precompute2<<<H / PR, NTHR>>>(cls1_w, cls1_b, ln_text_g, ln_text_b, ln_bio_g, ln_bio_b);
    convert_weights<<<(H * TXT + NTHR - 1) / NTHR, NTHR>>>(bio_w, text_w);

    cudaFuncSetAttribute(fused_main, cudaFuncAttributeMaxDynamicSharedMemorySize, SMEM_BYTES);
    fused_main<<<B / TM, NTHR, SMEM_BYTES>>>(bio, text, bio_b, text_b,
                                             cls_ln_g, cls_ln_b,
                                             cls2_w, cls2_b, out);
}

// round 10
// speedup vs baseline: 2.6868x; 1.2673x over previous
#include <cuda_runtime.h>
#include <cuda_bf16.h>

#define H      256
#define TXT    768
#define BIO    32
#define TM     64
#define NTHR   256
#define EPSLN  1e-5f
#define PRC    2

#define LDA3   520      // A3 smem pitch (bf16 elems)
#define LDT    40       // K-tile smem pitch (bf16 elems)

// ---------------- device scratch ----------------
__device__ float g_M [H * H];
__device__ float g_c [H];
__device__ float g_Ag[H * H];
__device__ float g_Bg[H * H];
__device__ float g_uA[H];
__device__ float g_uB[H];
__device__ float g_e [H];

__device__ __align__(16) __nv_bfloat16 g_W1h[H * BIO], g_W1l[H * BIO];
__device__ __align__(16) __nv_bfloat16 g_W2h[H * TXT], g_W2l[H * TXT];
__device__ __align__(16) __nv_bfloat16 g_W3h[H * 512], g_W3l[H * 512];

// ---------------- precompute 1 ----------------
__global__ void precompute1(const float* __restrict__ in_proj_w,
                            const float* __restrict__ in_proj_b,
                            const float* __restrict__ out_w,
                            const float* __restrict__ out_b) {
    __shared__ float s_row[PRC][H];
    __shared__ float s_part[8][PRC];
    const int i0 = blockIdx.x * PRC;
    const int j  = threadIdx.x;
    const int lane = j & 31, wrp = j >> 5;
#pragma unroll
    for (int r = 0; r < PRC; r++) s_row[r][j] = out_w[(i0 + r) * H + j];
    __syncthreads();
    float acc[PRC];
#pragma unroll
    for (int r = 0; r < PRC; r++) acc[r] = 0.f;
#pragma unroll 8
    for (int k = 0; k < H; k++) {
        float w = in_proj_w[(2 * H + k) * H + j];
#pragma unroll
        for (int r = 0; r < PRC; r++) acc[r] = fmaf(s_row[r][k], w, acc[r]);
    }
#pragma unroll
    for (int r = 0; r < PRC; r++) g_M[(i0 + r) * H + j] = acc[r];
    float bv = in_proj_b[2 * H + j];
#pragma unroll
    for (int r = 0; r < PRC; r++) {
        float v = s_row[r][j] * bv;
#pragma unroll
        for (int off = 16; off; off >>= 1) v += __shfl_xor_sync(0xffffffffu, v, off);
        if (lane == 0) s_part[wrp][r] = v;
    }
    __syncthreads();
    if (j < PRC) {
        float s = 0.f;
#pragma unroll
        for (int w = 0; w < 8; w++) s += s_part[w][j];
        g_c[i0 + j] = s + out_b[i0 + j];
    }
}

// ---------------- precompute 2 ----------------
__global__ void precompute2(const float* __restrict__ cls1_w,
                            const float* __restrict__ cls1_b,
                            const float* __restrict__ ln_text_g,
                            const float* __restrict__ ln_text_b,
                            const float* __restrict__ ln_bio_g,
                            const float* __restrict__ ln_bio_b) {
    __shared__ float s_l[PRC][H], s_r[PRC][H];
    __shared__ float s_part[8][3 * PRC];
    const int i0 = blockIdx.x * PRC;
    const int j  = threadIdx.x;
    const int lane = j & 31, wrp = j >> 5;
#pragma unroll
    for (int r = 0; r < PRC; r++) {
        s_l[r][j] = cls1_w[(i0 + r) * 2 * H + j];
        s_r[r][j] = cls1_w[(i0 + r) * 2 * H + H + j];
    }
    __syncthreads();
    float a[PRC], b[PRC];
#pragma unroll
    for (int r = 0; r < PRC; r++) { a[r] = 0.f; b[r] = 0.f; }
#pragma unroll 8
    for (int k = 0; k < H; k++) {
        float m = g_M[k * H + j];
#pragma unroll
        for (int r = 0; r < PRC; r++) {
            a[r] = fmaf(s_l[r][k], m, a[r]);
            b[r] = fmaf(s_r[r][k], m, b[r]);
        }
    }
    float gt = ln_text_g[j], gb = ln_bio_g[j];
    float lt = ln_text_b[j], lb = ln_bio_b[j];
    float cc = g_c[j];
    float vals[3 * PRC];
#pragma unroll
    for (int r = 0; r < PRC; r++) {
        float ag = a[r] * gt, bg = b[r] * gb;
        g_Ag[(i0 + r) * H + j] = ag;
        g_Bg[(i0 + r) * H + j] = bg;
        vals[r]           = ag;
        vals[PRC + r]     = bg;
        vals[2 * PRC + r] = a[r] * lt + b[r] * lb + (s_l[r][j] + s_r[r][j]) * cc;
    }
#pragma unroll
    for (int q = 0; q < 3 * PRC; q++) {
        float v = vals[q];
#pragma unroll
        for (int off = 16; off; off >>= 1) v += __shfl_xor_sync(0xffffffffu, v, off);
        if (lane == 0) s_part[wrp][q] = v;
    }
    __syncthreads();
    if (j < 3 * PRC) {
        float s = 0.f;
#pragma unroll
        for (int w = 0; w < 8; w++) s += s_part[w][j];
        int q = j / PRC, r = j % PRC;
        if (q == 0) g_uA[i0 + r] = s;
        else if (q == 1) g_uB[i0 + r] = s;
        else g_e[i0 + r] = s + cls1_b[i0 + r];
    }
}

// ---------------- precompute 3: bf16 hi/lo splits ----------------
__global__ void convert_weights(const float* __restrict__ bio_w,
                                const float* __restrict__ text_w) {
    int i = blockIdx.x * NTHR + threadIdx.x;
    if (i < H * BIO) {
        float v = bio_w[i];
        __nv_bfloat16 h = __float2bfloat16(v);
        g_W1h[i] = h;
        g_W1l[i] = __float2bfloat16(v - __bfloat162float(h));
    }
    if (i < H * 512) {
        int n = i >> 9, k = i & 511;
        float v = (k < H) ? g_Ag[n * H + k] : g_Bg[n * H + (k - H)];
        __nv_bfloat16 h = __float2bfloat16(v);
        g_W3h[i] = h;
        g_W3l[i] = __float2bfloat16(v - __bfloat162float(h));
    }
    if (i < H * TXT) {
        float v = text_w[i];
        __nv_bfloat16 h = __float2bfloat16(v);
        g_W2h[i] = h;
        g_W2l[i] = __float2bfloat16(v - __bfloat162float(h));
    }
}

// ---------------- mma helpers ----------------
__device__ __forceinline__ unsigned s2u(const void* p) {
    return (unsigned)__cvta_generic_to_shared(p);
}
__device__ __forceinline__ void ldsm4(unsigned* r, unsigned a) {
    asm volatile("ldmatrix.sync.aligned.m8n8.x4.shared.b16 {%0,%1,%2,%3}, [%4];"
                 : "=r"(r[0]), "=r"(r[1]), "=r"(r[2]), "=r"(r[3]) : "r"(a));
}
__device__ __forceinline__ void mma16816(float* d, const unsigned* a, const unsigned* b) {
    asm volatile("mma.sync.aligned.m16n8k16.row.col.f32.bf16.bf16.f32 "
                 "{%0,%1,%2,%3}, {%4,%5,%6,%7}, {%8,%9}, {%0,%1,%2,%3};"
                 : "+f"(d[0]), "+f"(d[1]), "+f"(d[2]), "+f"(d[3])
                 : "r"(a[0]), "r"(a[1]), "r"(a[2]), "r"(a[3]), "r"(b[0]), "r"(b[1]));
}
// one k16 step; warp tile M32xN64; 3-product hi/lo split
__device__ __forceinline__ void kstep2(unsigned aH, unsigned aL, int aMT,
                                       unsigned bH, unsigned bL,
                                       float (&acc)[2][8][4]) {
    unsigned ah[2][4], al[2][4];
    ldsm4(ah[0], aH);
    ldsm4(ah[1], aH + aMT);
    ldsm4(al[0], aL);
    ldsm4(al[1], aL + aMT);
#pragma unroll
    for (int p = 0; p < 4; p++) {
        unsigned bh[4], bl[4];
        ldsm4(bh, bH + p * (16 * LDT * 2));
        ldsm4(bl, bL + p * (16 * LDT * 2));
#pragma unroll
        for (int mt = 0; mt < 2; mt++) {
            mma16816(acc[mt][2 * p],     ah[mt], bh);
            mma16816(acc[mt][2 * p],     ah[mt], bl);
            mma16816(acc[mt][2 * p],     al[mt], bh);
            mma16816(acc[mt][2 * p + 1], ah[mt], bh + 2);
            mma16816(acc[mt][2 * p + 1], ah[mt], bl + 2);
            mma16816(acc[mt][2 * p + 1], al[mt], bh + 2);
        }
    }
}

// ---------------- staging (register double-buffer) ----------------
struct WPref { uint4 h[4], l[4]; };
__device__ __forceinline__ void ldg_w(WPref& p, const __nv_bfloat16* srcH,
                                      const __nv_bfloat16* srcL,
                                      int rowBytes, int k0, int tid) {
#pragma unroll
    for (int u = 0; u < 4; u++) {
        int qd = tid + u * NTHR, n = qd >> 2, c = qd & 3;
        p.h[u] = *(const uint4*)((const char*)srcH + n * rowBytes + k0 * 2 + c * 16);
        p.l[u] = *(const uint4*)((const char*)srcL + n * rowBytes + k0 * 2 + c * 16);
    }
}
__device__ __forceinline__ void sts_w(const WPref& p, __nv_bfloat16* Bh,
                                      __nv_bfloat16* Bl, int tid) {
#pragma unroll
    for (int u = 0; u < 4; u++) {
        int qd = tid + u * NTHR, n = qd >> 2, c = qd & 3;
        *(uint4*)((char*)Bh + n * 80 + c * 16) = p.h[u];
        *(uint4*)((char*)Bl + n * 80 + c * 16) = p.l[u];
    }
}
struct TPref { float4 v[2]; };
__device__ __forceinline__ void ldg_t(TPref& p, const float* text, int row0,
                                      int k0, int tid) {
#pragma unroll
    for (int u = 0; u < 2; u++) {
        int qd = tid + u * NTHR, r = qd >> 3, kq = qd & 7;
        p.v[u] = *(const float4*)&text[(row0 + r) * TXT + k0 + kq * 4];
    }
}
__device__ __forceinline__ void sts_t(const TPref& p, __nv_bfloat16* A2h,
                                      __nv_bfloat16* A2l, int tid) {
#pragma unroll
    for (int u = 0; u < 2; u++) {
        int qd = tid + u * NTHR, r = qd >> 3, kq = qd & 7;
        float vv[4] = {p.v[u].x, p.v[u].y, p.v[u].z, p.v[u].w};
#pragma unroll
        for (int i = 0; i < 4; i++) {
            __nv_bfloat16 h = __float2bfloat16(vv[i]);
            A2h[r * LDT + kq * 4 + i] = h;
            A2l[r * LDT + kq * 4 + i] = __float2bfloat16(vv[i] - __bfloat162float(h));
        }
    }
}

// ---------------- smem layout (byte offsets) ----------------
#define OFF_A3H 0
#define OFF_A3L 66560
#define OFF_A2H 133120
#define OFF_A2L 138240
#define OFF_BH  143360
#define OFF_BL  163840
#define OFF_VEC 184320
#define OFF_SS  193536
#define OFF_SQ  194560
#define OFF_AT  195584
#define OFF_AB  195840
#define OFF_HD  196096
#define SMEM_BYTES 198144

#define V_TB 0
#define V_BB 256
#define V_UA 512
#define V_UB 768
#define V_E  1024
#define V_CG 1280
#define V_CB 1536
#define V_C2 1792

// bias add + LN + hi/lo writeback into A3
__device__ __forceinline__ void ln_writeback(
    float (&acc)[2][8][4], const float* bias, float* statS, float* statQ,
    __nv_bfloat16* A3h, __nv_bfloat16* A3l, int colBase, float* alpha,
    int wm, int wn, int lane) {
    const int q = lane & 3, rq = lane >> 2;
    const int cb0 = wn * 64 + 2 * q;
#pragma unroll
    for (int mt = 0; mt < 2; mt++)
#pragma unroll
        for (int nt = 0; nt < 8; nt++) {
            int c = cb0 + nt * 8;
            float b0 = bias[c], b1 = bias[c + 1];
            acc[mt][nt][0] += b0; acc[mt][nt][1] += b1;
            acc[mt][nt][2] += b0; acc[mt][nt][3] += b1;
        }
    float s[4], qs[4];
#pragma unroll
    for (int mt = 0; mt < 2; mt++) {
        float s0 = 0, q0 = 0, s1 = 0, q1 = 0;
#pragma unroll
        for (int nt = 0; nt < 8; nt++) {
            s0 += acc[mt][nt][0] + acc[mt][nt][1];
            s1 += acc[mt][nt][2] + acc[mt][nt][3];
            q0 = fmaf(acc[mt][nt][0], acc[mt][nt][0], fmaf(acc[mt][nt][1], acc[mt][nt][1], q0));
            q1 = fmaf(acc[mt][nt][2], acc[mt][nt][2], fmaf(acc[mt][nt][3], acc[mt][nt][3], q1));
        }
        s[mt * 2] = s0; qs[mt * 2] = q0; s[mt * 2 + 1] = s1; qs[mt * 2 + 1] = q1;
    }
#pragma unroll
    for (int o = 1; o <= 2; o <<= 1)
#pragma unroll
        for (int i = 0; i < 4; i++) {
            s[i]  += __shfl_xor_sync(0xffffffffu, s[i], o);
            qs[i] += __shfl_xor_sync(0xffffffffu, qs[i], o);
        }
    if (q == 0) {
#pragma unroll
        for (int i = 0; i < 4; i++) {
            int r = wm * 32 + (i >> 1) * 16 + rq + (i & 1) * 8;
            statS[wn * 64 + r] = s[i];
            statQ[wn * 64 + r] = qs[i];
        }
    }
    __syncthreads();
    float inv[4];
#pragma unroll
    for (int i = 0; i < 4; i++) {
        int r = wm * 32 + (i >> 1) * 16 + rq + (i & 1) * 8;
        float S = statS[r] + statS[64 + r] + statS[128 + r] + statS[192 + r];
        float Q = statQ[r] + statQ[64 + r] + statQ[128 + r] + statQ[192 + r];
        float m = S * (1.f / H);
        float iv = rsqrtf(fmaf(Q, 1.f / H, -m * m) + EPSLN);
        inv[i] = iv;
        if (q == 0 && wn == 0) alpha[r] = -iv * m;
    }
#pragma unroll
    for (int mt = 0; mt < 2; mt++)
#pragma unroll
        for (int nt = 0; nt < 8; nt++) {
            int c = colBase + cb0 + nt * 8;
#pragma unroll
            for (int h = 0; h < 2; h++) {
                int r = wm * 32 + mt * 16 + rq + h * 8;
                float iv = inv[mt * 2 + h];
#pragma unroll
                for (int d = 0; d < 2; d++) {
                    float v = acc[mt][nt][2 * h + d] * iv;
                    __nv_bfloat16 hh = __float2bfloat16(v);
                    A3h[r * LDA3 + c + d] = hh;
                    A3l[r * LDA3 + c + d] = __float2bfloat16(v - __bfloat162float(hh));
                }
            }
        }
}

// ---------------- main fused kernel ----------------
__global__ __launch_bounds__(NTHR, 1)
void fused_main(const float* __restrict__ bio,
                const float* __restrict__ text,
                const float* __restrict__ bio_b,
                const float* __restrict__ text_b,
                const float* __restrict__ cls_ln_g,
                const float* __restrict__ cls_ln_b,
                const float* __restrict__ cls2_w,
                const float* __restrict__ cls2_b,
                float* __restrict__ out) {
    extern __shared__ char sm[];
    __nv_bfloat16* A3h = (__nv_bfloat16*)(sm + OFF_A3H);
    __nv_bfloat16* A3l = (__nv_bfloat16*)(sm + OFF_A3L);
    __nv_bfloat16* A2h = (__nv_bfloat16*)(sm + OFF_A2H);
    __nv_bfloat16* A2l = (__nv_bfloat16*)(sm + OFF_A2L);
    __nv_bfloat16* Bh  = (__nv_bfloat16*)(sm + OFF_BH);
    __nv_bfloat16* Bl  = (__nv_bfloat16*)(sm + OFF_BL);
    float* vec   = (float*)(sm + OFF_VEC);
    float* statS = (float*)(sm + OFF_SS);
    float* statQ = (float*)(sm + OFF_SQ);
    float* s_at  = (float*)(sm + OFF_AT);
    float* s_ab  = (float*)(sm + OFF_AB);
    float* s_hd  = (float*)(sm + OFF_HD);

    const int tid  = threadIdx.x;
    const int lane = tid & 31, wid = tid >> 5;
    const int wm = wid >> 2;          // 0..1 (M32 groups)
    const int wn = wid & 3;           // 0..3 (N64 groups)
    const int row0 = blockIdx.x * TM;

    const int aRowL = lane & 15;
    const int aKoff = (lane >> 4) << 3;
    const int bNoff = ((lane >> 4) << 3) + (lane & 7);
    const int bKoff = ((lane >> 3) & 1) << 3;

    const float c2b0 = cls2_b[0];
    const float c2b1 = cls2_b[1];

    const unsigned uA3h = s2u(A3h) + ((wm * 32 + aRowL) * LDA3 + aKoff) * 2;
    const unsigned uA3l = s2u(A3l) + ((wm * 32 + aRowL) * LDA3 + aKoff) * 2;
    const unsigned uA2h = s2u(A2h) + ((wm * 32 + aRowL) * LDT + aKoff) * 2;
    const unsigned uA2l = s2u(A2l) + ((wm * 32 + aRowL) * LDT + aKoff) * 2;
    const unsigned uBh  = s2u(Bh)  + ((wn * 64 + bNoff) * LDT + bKoff) * 2;
    const unsigned uBl  = s2u(Bl)  + ((wn * 64 + bNoff) * LDT + bKoff) * 2;
    const int aMT2 = 16 * LDT * 2;    // phase-1/2 A m-tile stride (bytes)
    const int aMT3 = 16 * LDA3 * 2;   // phase-3 A m-tile stride (bytes)

    // ---- phase 0: stage vectors + bio + W1 directly ----
    vec[V_TB + tid] = text_b[tid];
    vec[V_BB + tid] = bio_b[tid];
    vec[V_UA + tid] = g_uA[tid];
    vec[V_UB + tid] = g_uB[tid];
    vec[V_E  + tid] = g_e[tid];
    vec[V_CG + tid] = cls_ln_g[tid];
    vec[V_CB + tid] = cls_ln_b[tid];
    vec[V_C2 + tid]       = cls2_w[tid];
    vec[V_C2 + 256 + tid] = cls2_w[256 + tid];

#pragma unroll
    for (int u = 0; u < 2; u++) {                       // bio 64x32 fp32 -> A2 hi/lo
        int qd = tid + u * NTHR;
        int r = qd >> 3, kq = qd & 7;
        float4 v = *(const float4*)&bio[(row0 + r) * BIO + kq * 4];
        float vv[4] = {v.x, v.y, v.z, v.w};
#pragma unroll
        for (int i = 0; i < 4; i++) {
            __nv_bfloat16 h = __float2bfloat16(vv[i]);
            A2h[r * LDT + kq * 4 + i] = h;
            A2l[r * LDT + kq * 4 + i] = __float2bfloat16(vv[i] - __bfloat162float(h));
        }
    }
#pragma unroll
    for (int u = 0; u < 4; u++) {                       // W1 256x32 bf16 hi/lo
        int qd = tid + u * NTHR;
        int n = qd >> 2, c = qd & 3;
        *(uint4*)((char*)Bh + n * 80 + c * 16) = *(const uint4*)((const char*)g_W1h + n * 64 + c * 16);
        *(uint4*)((char*)Bl + n * 80 + c * 16) = *(const uint4*)((const char*)g_W1l + n * 64 + c * 16);
    }
    __syncthreads();

    // prefetch W2 tile 0 + text tile 0 (hidden under phase-1 compute)
    WPref pw;  TPref pt;
    ldg_w(pw, g_W2h, g_W2l, TXT * 2, 0, tid);
    ldg_t(pt, text, row0, 0, tid);

    float acc[2][8][4];

    // ---- phase 1: bio GEMM (K=32) ----
#pragma unroll
    for (int mt = 0; mt < 2; mt++)
#pragma unroll
        for (int nt = 0; nt < 8; nt++)
#pragma unroll
            for (int j = 0; j < 4; j++) acc[mt][nt][j] = 0.f;
    kstep2(uA2h,      uA2l,      aMT2, uBh,      uBl,      acc);
    kstep2(uA2h + 32, uA2l + 32, aMT2, uBh + 32, uBl + 32, acc);
    ln_writeback(acc, vec + V_BB, statS, statQ, A3h, A3l, 256, s_ab, wm, wn, lane);

    // ---- phase 2: text GEMM (K=768, 24 tiles) ----
#pragma unroll
    for (int mt = 0; mt < 2; mt++)
#pragma unroll
        for (int nt = 0; nt < 8; nt++)
#pragma unroll
            for (int j = 0; j < 4; j++) acc[mt][nt][j] = 0.f;

    for (int kt = 0; kt < 24; kt++) {
        __syncthreads();                   // readers of previous tile done
        sts_w(pw, Bh, Bl, tid);
        sts_t(pt, A2h, A2l, tid);
        __syncthreads();
        if (kt < 23) {                     // prefetch next (hidden under MMAs)
            ldg_w(pw, g_W2h, g_W2l, TXT * 2, (kt + 1) * 32, tid);
            ldg_t(pt, text, row0, (kt + 1) * 32, tid);
        } else {
            ldg_w(pw, g_W3h, g_W3l, 1024, 0, tid);
        }
        kstep2(uA2h,      uA2l,      aMT2, uBh,      uBl,      acc);
        kstep2(uA2h + 32, uA2l + 32, aMT2, uBh + 32, uBl + 32, acc);
    }
    __syncthreads();
    ln_writeback(acc, vec + V_TB, statS, statQ, A3h, A3l, 0, s_at, wm, wn, lane);

    // ---- phase 3: classifier GEMM (K=512, 16 tiles) ----
#pragma unroll
    for (int mt = 0; mt < 2; mt++)
#pragma unroll
        for (int nt = 0; nt < 8; nt++)
#pragma unroll
            for (int j = 0; j < 4; j++) acc[mt][nt][j] = 0.f;

    for (int kt = 0; kt < 16; kt++) {
        __syncthreads();
        sts_w(pw, Bh, Bl, tid);
        __syncthreads();
        if (kt < 15) ldg_w(pw, g_W3h, g_W3l, 1024, (kt + 1) * 32, tid);
        unsigned a3h = uA3h + kt * 64;     // kt*32 elems * 2B
        unsigned a3l = uA3l + kt * 64;
        kstep2(a3h,      a3l,      aMT3, uBh,      uBl,      acc);
        kstep2(a3h + 32, a3l + 32, aMT3, uBh + 32, uBl + 32, acc);
    }

    // ---- phase 4: rank-1 corrections, final LN + ReLU + head ----
    const int q = lane & 3, rq = lane >> 2;
    float at4[4], ab4[4];
#pragma unroll
    for (int i = 0; i < 4; i++) {
        int r = wm * 32 + (i >> 1) * 16 + rq + (i & 1) * 8;
        at4[i] = s_at[r];
        ab4[i] = s_ab[r];
    }
#pragma unroll
    for (int mt = 0; mt < 2; mt++)
#pragma unroll
        for (int nt = 0; nt < 8; nt++) {
            int c = wn * 64 + nt * 8 + 2 * q;
#pragma unroll
            for (int d = 0; d < 2; d++) {
                float uA = vec[V_UA + c + d];
                float uB = vec[V_UB + c + d];
                float e  = vec[V_E  + c + d];
#pragma unroll
                for (int h = 0; h < 2; h++) {
                    int i = mt * 2 + h;
                    acc[mt][nt][2 * h + d] =
                        fmaf(at4[i], uA, fmaf(ab4[i], uB, acc[mt][nt][2 * h + d] + e));
                }
            }
        }
    // final LN stats
    float s4[4], q4[4];
#pragma unroll
    for (int mt = 0; mt < 2; mt++) {
        float s0 = 0, q0 = 0, s1 = 0, q1 = 0;
#pragma unroll
        for (int nt = 0; nt < 8; nt++) {
            s0 += acc[mt][nt][0] + acc[mt][nt][1];
            s1 += acc[mt][nt][2] + acc[mt][nt][3];
            q0 = fmaf(acc[mt][nt][0], acc[mt][nt][0], fmaf(acc[mt][nt][1], acc[mt][nt][1], q0));
            q1 = fmaf(acc[mt][nt][2], acc[mt][nt][2], fmaf(acc[mt][nt][3], acc[mt][nt][3], q1));
        }
        s4[mt * 2] = s0; q4[mt * 2] = q0; s4[mt * 2 + 1] = s1; q4[mt * 2 + 1] = q1;
    }
#pragma unroll
    for (int o = 1; o <= 2; o <<= 1)
#pragma unroll
        for (int i = 0; i < 4; i++) {
            s4[i] += __shfl_xor_sync(0xffffffffu, s4[i], o);
            q4[i] += __shfl_xor_sync(0xffffffffu, q4[i], o);
        }
    if (q == 0) {
#pragma unroll
        for (int i = 0; i < 4; i++) {
            int r = wm * 32 + (i >> 1) * 16 + rq + (i & 1) * 8;
            statS[wn * 64 + r] = s4[i];
            statQ[wn * 64 + r] = q4[i];
        }
    }
    __syncthreads();
    float mm[4], iv4[4];
#pragma unroll
    for (int i = 0; i < 4; i++) {
        int r = wm * 32 + (i >> 1) * 16 + rq + (i & 1) * 8;
        float S = statS[r] + statS[64 + r] + statS[128 + r] + statS[192 + r];
        float Q = statQ[r] + statQ[64 + r] + statQ[128 + r] + statQ[192 + r];
        mm[i]  = S * (1.f / H);
        iv4[i] = rsqrtf(fmaf(Q, 1.f / H, -mm[i] * mm[i]) + EPSLN);
    }
    float p0[4] = {0, 0, 0, 0}, p1[4] = {0, 0, 0, 0};
#pragma unroll
    for (int mt = 0; mt < 2; mt++)
#pragma unroll
        for (int nt = 0; nt < 8; nt++) {
            int c = wn * 64 + nt * 8 + 2 * q;
#pragma unroll
            for (int d = 0; d < 2; d++) {
                float cg = vec[V_CG + c + d], cb = vec[V_CB + c + d];
                float w0 = vec[V_C2 + c + d], w1 = vec[V_C2 + 256 + c + d];
#pragma unroll
                for (int h = 0; h < 2; h++) {
                    int i = mt * 2 + h;
                    float hv = fmaf((acc[mt][nt][2 * h + d] - mm[i]) * iv4[i], cg, cb);
                    hv = fmaxf(hv, 0.f);
                    p0[i] = fmaf(hv, w0, p0[i]);
                    p1[i] = fmaf(hv, w1, p1[i]);
                }
            }
        }
#pragma unroll
    for (int o = 1; o <= 2; o <<= 1)
#pragma unroll
        for (int i = 0; i < 4; i++) {
            p0[i] += __shfl_xor_sync(0xffffffffu, p0[i], o);
            p1[i] += __shfl_xor_sync(0xffffffffu, p1[i], o);
        }
    if (q == 0) {
#pragma unroll
        for (int i = 0; i < 4; i++) {
            int r = wm * 32 + (i >> 1) * 16 + rq + (i & 1) * 8;
            s_hd[wn * 128 + r * 2]     = p0[i];
            s_hd[wn * 128 + r * 2 + 1] = p1[i];
        }
    }
    __syncthreads();
    if (tid < TM) {
        int r = row0 + tid;
        out[2 * r]     = s_hd[tid * 2]     + s_hd[128 + tid * 2] +
                         s_hd[256 + tid * 2] + s_hd[384 + tid * 2] + c2b0;
        out[2 * r + 1] = s_hd[tid * 2 + 1] + s_hd[128 + tid * 2 + 1] +
                         s_hd[256 + tid * 2 + 1] + s_hd[384 + tid * 2 + 1] + c2b1;
    }
}

// ---------------- launch ----------------
extern "C" void kernel_launch(void* const* d_in, const int* in_sizes, int n_in,
                              void* d_out, int out_size) {
    const float* bio       = (const float*)d_in[0];
    const float* text      = (const float*)d_in[1];
    const float* bio_w     = (const float*)d_in[2];
    const float* bio_b     = (const float*)d_in[3];
    const float* text_w    = (const float*)d_in[4];
    const float* text_b    = (const float*)d_in[5];
    const float* ln_bio_g  = (const float*)d_in[6];
    const float* ln_bio_b  = (const float*)d_in[7];
    const float* ln_text_g = (const float*)d_in[8];
    const float* ln_text_b = (const float*)d_in[9];
    const float* in_proj_w = (const float*)d_in[10];
    const float* in_proj_b = (const float*)d_in[11];
    const float* out_w     = (const float*)d_in[12];
    const float* out_b     = (const float*)d_in[13];
    const float* cls1_w    = (const float*)d_in[14];
    const float* cls1_b    = (const float*)d_in[15];
    const float* cls_ln_g  = (const float*)d_in[16];
    const float* cls_ln_b  = (const float*)d_in[17];
    const float* cls2_w    = (const float*)d_in[18];
    const float* cls2_b    = (const float*)d_in[19];
    float* out = (float*)d_out;

    const int B = in_sizes[0] / BIO;   // 65536

    precompute1<<<H / PRC, NTHR>>>(in_proj_w, in_proj_b, out_w, out_b);
    precompute2<<<H / PRC, NTHR>>>(cls1_w, cls1_b, ln_text_g, ln_text_b, ln_bio_g, ln_bio_b);
    convert_weights<<<(H * TXT + NTHR - 1) / NTHR, NTHR>>>(bio_w, text_w);

    cudaFuncSetAttribute(fused_main, cudaFuncAttributeMaxDynamicSharedMemorySize, SMEM_BYTES);
    fused_main<<<B / TM, NTHR, SMEM_BYTES>>>(bio, text, bio_b, text_b,
                                             cls_ln_g, cls_ln_b,
                                             cls2_w, cls2_b, out);
}

// round 11
// speedup vs baseline: 4.2396x; 1.5779x over previous
#include <cuda_runtime.h>
#include <cuda_fp16.h>

#define H      256
#define TXT    768
#define BIO    32
#define TM     64
#define NTHR   256
#define EPSLN  1e-5f
#define PRC    2

#define LDA3   520      // A3 smem pitch (half elems)
#define LDT    40       // K-tile smem pitch (half elems)

// ---------------- device scratch ----------------
__device__ float g_M [H * H];
__device__ float g_c [H];
__device__ float g_Ag[H * H];
__device__ float g_Bg[H * H];
__device__ float g_uA[H];
__device__ float g_uB[H];
__device__ float g_e [H];

__device__ __align__(16) __half g_W1h[H * BIO];
__device__ __align__(16) __half g_W2h[H * TXT];
__device__ __align__(16) __half g_W3h[H * 512];

// ---------------- precompute 1 ----------------
__global__ void precompute1(const float* __restrict__ in_proj_w,
                            const float* __restrict__ in_proj_b,
                            const float* __restrict__ out_w,
                            const float* __restrict__ out_b) {
    __shared__ float s_row[PRC][H];
    __shared__ float s_part[8][PRC];
    const int i0 = blockIdx.x * PRC;
    const int j  = threadIdx.x;
    const int lane = j & 31, wrp = j >> 5;
#pragma unroll
    for (int r = 0; r < PRC; r++) s_row[r][j] = out_w[(i0 + r) * H + j];
    __syncthreads();
    float acc[PRC];
#pragma unroll
    for (int r = 0; r < PRC; r++) acc[r] = 0.f;
#pragma unroll 8
    for (int k = 0; k < H; k++) {
        float w = in_proj_w[(2 * H + k) * H + j];
#pragma unroll
        for (int r = 0; r < PRC; r++) acc[r] = fmaf(s_row[r][k], w, acc[r]);
    }
#pragma unroll
    for (int r = 0; r < PRC; r++) g_M[(i0 + r) * H + j] = acc[r];
    float bv = in_proj_b[2 * H + j];
#pragma unroll
    for (int r = 0; r < PRC; r++) {
        float v = s_row[r][j] * bv;
#pragma unroll
        for (int off = 16; off; off >>= 1) v += __shfl_xor_sync(0xffffffffu, v, off);
        if (lane == 0) s_part[wrp][r] = v;
    }
    __syncthreads();
    if (j < PRC) {
        float s = 0.f;
#pragma unroll
        for (int w = 0; w < 8; w++) s += s_part[w][j];
        g_c[i0 + j] = s + out_b[i0 + j];
    }
}

// ---------------- precompute 2 ----------------
__global__ void precompute2(const float* __restrict__ cls1_w,
                            const float* __restrict__ cls1_b,
                            const float* __restrict__ ln_text_g,
                            const float* __restrict__ ln_text_b,
                            const float* __restrict__ ln_bio_g,
                            const float* __restrict__ ln_bio_b) {
    __shared__ float s_l[PRC][H], s_r[PRC][H];
    __shared__ float s_part[8][3 * PRC];
    const int i0 = blockIdx.x * PRC;
    const int j  = threadIdx.x;
    const int lane = j & 31, wrp = j >> 5;
#pragma unroll
    for (int r = 0; r < PRC; r++) {
        s_l[r][j] = cls1_w[(i0 + r) * 2 * H + j];
        s_r[r][j] = cls1_w[(i0 + r) * 2 * H + H + j];
    }
    __syncthreads();
    float a[PRC], b[PRC];
#pragma unroll
    for (int r = 0; r < PRC; r++) { a[r] = 0.f; b[r] = 0.f; }
#pragma unroll 8
    for (int k = 0; k < H; k++) {
        float m = g_M[k * H + j];
#pragma unroll
        for (int r = 0; r < PRC; r++) {
            a[r] = fmaf(s_l[r][k], m, a[r]);
            b[r] = fmaf(s_r[r][k], m, b[r]);
        }
    }
    float gt = ln_text_g[j], gb = ln_bio_g[j];
    float lt = ln_text_b[j], lb = ln_bio_b[j];
    float cc = g_c[j];
    float vals[3 * PRC];
#pragma unroll
    for (int r = 0; r < PRC; r++) {
        float ag = a[r] * gt, bg = b[r] * gb;
        g_Ag[(i0 + r) * H + j] = ag;
        g_Bg[(i0 + r) * H + j] = bg;
        vals[r]           = ag;
        vals[PRC + r]     = bg;
        vals[2 * PRC + r] = a[r] * lt + b[r] * lb + (s_l[r][j] + s_r[r][j]) * cc;
    }
#pragma unroll
    for (int q = 0; q < 3 * PRC; q++) {
        float v = vals[q];
#pragma unroll
        for (int off = 16; off; off >>= 1) v += __shfl_xor_sync(0xffffffffu, v, off);
        if (lane == 0) s_part[wrp][q] = v;
    }
    __syncthreads();
    if (j < 3 * PRC) {
        float s = 0.f;
#pragma unroll
        for (int w = 0; w < 8; w++) s += s_part[w][j];
        int q = j / PRC, r = j % PRC;
        if (q == 0) g_uA[i0 + r] = s;
        else if (q == 1) g_uB[i0 + r] = s;
        else g_e[i0 + r] = s + cls1_b[i0 + r];
    }
}

// ---------------- precompute 3: fp16 weight casts ----------------
__global__ void convert_weights(const float* __restrict__ bio_w,
                                const float* __restrict__ text_w) {
    int i = blockIdx.x * NTHR + threadIdx.x;
    if (i < H * BIO)  g_W1h[i] = __float2half_rn(bio_w[i]);
    if (i < H * 512) {
        int n = i >> 9, k = i & 511;
        float v = (k < H) ? g_Ag[n * H + k] : g_Bg[n * H + (k - H)];
        g_W3h[i] = __float2half_rn(v);
    }
    if (i < H * TXT)  g_W2h[i] = __float2half_rn(text_w[i]);
}

// ---------------- mma helpers ----------------
__device__ __forceinline__ unsigned s2u(const void* p) {
    return (unsigned)__cvta_generic_to_shared(p);
}
__device__ __forceinline__ void ldsm4(unsigned* r, unsigned a) {
    asm volatile("ldmatrix.sync.aligned.m8n8.x4.shared.b16 {%0,%1,%2,%3}, [%4];"
                 : "=r"(r[0]), "=r"(r[1]), "=r"(r[2]), "=r"(r[3]) : "r"(a));
}
__device__ __forceinline__ void mma16816(float* d, const unsigned* a, const unsigned* b) {
    asm volatile("mma.sync.aligned.m16n8k16.row.col.f32.f16.f16.f32 "
                 "{%0,%1,%2,%3}, {%4,%5,%6,%7}, {%8,%9}, {%0,%1,%2,%3};"
                 : "+f"(d[0]), "+f"(d[1]), "+f"(d[2]), "+f"(d[3])
                 : "r"(a[0]), "r"(a[1]), "r"(a[2]), "r"(a[3]), "r"(b[0]), "r"(b[1]));
}
// one k16 step; warp tile M32xN64; A hi/lo 2-product, B hi only
__device__ __forceinline__ void kstep2(unsigned aH, unsigned aL, int aMT,
                                       unsigned bH, float (&acc)[2][8][4]) {
    unsigned ah[2][4], al[2][4];
    ldsm4(ah[0], aH);
    ldsm4(ah[1], aH + aMT);
    ldsm4(al[0], aL);
    ldsm4(al[1], aL + aMT);
#pragma unroll
    for (int p = 0; p < 4; p++) {
        unsigned bh[4];
        ldsm4(bh, bH + p * (16 * LDT * 2));
#pragma unroll
        for (int mt = 0; mt < 2; mt++) {
            mma16816(acc[mt][2 * p],     ah[mt], bh);
            mma16816(acc[mt][2 * p],     al[mt], bh);
            mma16816(acc[mt][2 * p + 1], ah[mt], bh + 2);
            mma16816(acc[mt][2 * p + 1], al[mt], bh + 2);
        }
    }
}

// ---------------- staging (register prefetch) ----------------
struct WPref { uint4 h[4]; };
__device__ __forceinline__ void ldg_w(WPref& p, const __half* srcH,
                                      int rowBytes, int k0, int tid) {
#pragma unroll
    for (int u = 0; u < 4; u++) {
        int qd = tid + u * NTHR, n = qd >> 2, c = qd & 3;
        p.h[u] = *(const uint4*)((const char*)srcH + n * rowBytes + k0 * 2 + c * 16);
    }
}
__device__ __forceinline__ void sts_w(const WPref& p, __half* Bh, int tid) {
#pragma unroll
    for (int u = 0; u < 4; u++) {
        int qd = tid + u * NTHR, n = qd >> 2, c = qd & 3;
        *(uint4*)((char*)Bh + n * 80 + c * 16) = p.h[u];
    }
}
struct TPref { float4 v[2]; };
__device__ __forceinline__ void ldg_t(TPref& p, const float* text, int row0,
                                      int k0, int tid) {
#pragma unroll
    for (int u = 0; u < 2; u++) {
        int qd = tid + u * NTHR, r = qd >> 3, kq = qd & 7;
        p.v[u] = *(const float4*)&text[(row0 + r) * TXT + k0 + kq * 4];
    }
}
__device__ __forceinline__ void sts_t(const TPref& p, __half* A2h,
                                      __half* A2l, int tid) {
#pragma unroll
    for (int u = 0; u < 2; u++) {
        int qd = tid + u * NTHR, r = qd >> 3, kq = qd & 7;
        float vv[4] = {p.v[u].x, p.v[u].y, p.v[u].z, p.v[u].w};
#pragma unroll
        for (int i = 0; i < 4; i++) {
            __half h = __float2half_rn(vv[i]);
            A2h[r * LDT + kq * 4 + i] = h;
            A2l[r * LDT + kq * 4 + i] = __float2half_rn(vv[i] - __half2float(h));
        }
    }
}

// ---------------- smem layout (byte offsets) ----------------
#define OFF_A3H 0
#define OFF_A3L 66560
#define OFF_BH  133120       // 2 bufs x 20480
#define BUF_WB  20480
#define OFF_A2H 174080       // 2 bufs x 5120
#define OFF_A2L 184320       // 2 bufs x 5120
#define BUF_AB  5120
#define OFF_VEC 194560
#define OFF_SS  203776
#define OFF_SQ  204800
#define OFF_AT  205824
#define OFF_AB2 206080
#define OFF_HD  206336
#define SMEM_BYTES 208384

#define V_TB 0
#define V_BB 256
#define V_UA 512
#define V_UB 768
#define V_E  1024
#define V_CG 1280
#define V_CB 1536
#define V_C2 1792

// bias add + LN + fp16 hi/lo writeback into A3
__device__ __forceinline__ void ln_writeback(
    float (&acc)[2][8][4], const float* bias, float* statS, float* statQ,
    __half* A3h, __half* A3l, int colBase, float* alpha,
    int wm, int wn, int lane) {
    const int q = lane & 3, rq = lane >> 2;
    const int cb0 = wn * 64 + 2 * q;
#pragma unroll
    for (int mt = 0; mt < 2; mt++)
#pragma unroll
        for (int nt = 0; nt < 8; nt++) {
            int c = cb0 + nt * 8;
            float b0 = bias[c], b1 = bias[c + 1];
            acc[mt][nt][0] += b0; acc[mt][nt][1] += b1;
            acc[mt][nt][2] += b0; acc[mt][nt][3] += b1;
        }
    float s[4], qs[4];
#pragma unroll
    for (int mt = 0; mt < 2; mt++) {
        float s0 = 0, q0 = 0, s1 = 0, q1 = 0;
#pragma unroll
        for (int nt = 0; nt < 8; nt++) {
            s0 += acc[mt][nt][0] + acc[mt][nt][1];
            s1 += acc[mt][nt][2] + acc[mt][nt][3];
            q0 = fmaf(acc[mt][nt][0], acc[mt][nt][0], fmaf(acc[mt][nt][1], acc[mt][nt][1], q0));
            q1 = fmaf(acc[mt][nt][2], acc[mt][nt][2], fmaf(acc[mt][nt][3], acc[mt][nt][3], q1));
        }
        s[mt * 2] = s0; qs[mt * 2] = q0; s[mt * 2 + 1] = s1; qs[mt * 2 + 1] = q1;
    }
#pragma unroll
    for (int o = 1; o <= 2; o <<= 1)
#pragma unroll
        for (int i = 0; i < 4; i++) {
            s[i]  += __shfl_xor_sync(0xffffffffu, s[i], o);
            qs[i] += __shfl_xor_sync(0xffffffffu, qs[i], o);
        }
    if (q == 0) {
#pragma unroll
        for (int i = 0; i < 4; i++) {
            int r = wm * 32 + (i >> 1) * 16 + rq + (i & 1) * 8;
            statS[wn * 64 + r] = s[i];
            statQ[wn * 64 + r] = qs[i];
        }
    }
    __syncthreads();
    float inv[4];
#pragma unroll
    for (int i = 0; i < 4; i++) {
        int r = wm * 32 + (i >> 1) * 16 + rq + (i & 1) * 8;
        float S = statS[r] + statS[64 + r] + statS[128 + r] + statS[192 + r];
        float Q = statQ[r] + statQ[64 + r] + statQ[128 + r] + statQ[192 + r];
        float m = S * (1.f / H);
        float iv = rsqrtf(fmaf(Q, 1.f / H, -m * m) + EPSLN);
        inv[i] = iv;
        if (q == 0 && wn == 0) alpha[r] = -iv * m;
    }
#pragma unroll
    for (int mt = 0; mt < 2; mt++)
#pragma unroll
        for (int nt = 0; nt < 8; nt++) {
            int c = colBase + cb0 + nt * 8;
#pragma unroll
            for (int h = 0; h < 2; h++) {
                int r = wm * 32 + mt * 16 + rq + h * 8;
                float iv = inv[mt * 2 + h];
#pragma unroll
                for (int d = 0; d < 2; d++) {
                    float v = acc[mt][nt][2 * h + d] * iv;
                    __half hh = __float2half_rn(v);
                    A3h[r * LDA3 + c + d] = hh;
                    A3l[r * LDA3 + c + d] = __float2half_rn(v - __half2float(hh));
                }
            }
        }
}

// ---------------- main fused kernel ----------------
__global__ __launch_bounds__(NTHR, 1)
void fused_main(const float* __restrict__ bio,
                const float* __restrict__ text,
                const float* __restrict__ bio_b,
                const float* __restrict__ text_b,
                const float* __restrict__ cls_ln_g,
                const float* __restrict__ cls_ln_b,
                const float* __restrict__ cls2_w,
                const float* __restrict__ cls2_b,
                float* __restrict__ out) {
    extern __shared__ char sm[];
    __half* A3h = (__half*)(sm + OFF_A3H);
    __half* A3l = (__half*)(sm + OFF_A3L);
    __half* Bh  = (__half*)(sm + OFF_BH);
    __half* A2h = (__half*)(sm + OFF_A2H);
    __half* A2l = (__half*)(sm + OFF_A2L);
    float* vec   = (float*)(sm + OFF_VEC);
    float* statS = (float*)(sm + OFF_SS);
    float* statQ = (float*)(sm + OFF_SQ);
    float* s_at  = (float*)(sm + OFF_AT);
    float* s_ab  = (float*)(sm + OFF_AB2);
    float* s_hd  = (float*)(sm + OFF_HD);

    const int tid  = threadIdx.x;
    const int lane = tid & 31, wid = tid >> 5;
    const int wm = wid >> 2;          // 0..1
    const int wn = wid & 3;           // 0..3
    const int row0 = blockIdx.x * TM;

    const int aRowL = lane & 15;
    const int aKoff = (lane >> 4) << 3;
    const int bNoff = ((lane >> 4) << 3) + (lane & 7);
    const int bKoff = ((lane >> 3) & 1) << 3;

    const float c2b0 = cls2_b[0];
    const float c2b1 = cls2_b[1];

    const unsigned uA3h = s2u(A3h) + ((wm * 32 + aRowL) * LDA3 + aKoff) * 2;
    const unsigned uA3l = s2u(A3l) + ((wm * 32 + aRowL) * LDA3 + aKoff) * 2;
    const unsigned uA2h = s2u(A2h) + ((wm * 32 + aRowL) * LDT + aKoff) * 2;
    const unsigned uA2l = s2u(A2l) + ((wm * 32 + aRowL) * LDT + aKoff) * 2;
    const unsigned uBh  = s2u(Bh)  + ((wn * 64 + bNoff) * LDT + bKoff) * 2;
    const int aMT2 = 16 * LDT * 2;
    const int aMT3 = 16 * LDA3 * 2;

    // ---- phase 0: vectors + bio (buf1) + W1 (buf1) ----
    vec[V_TB + tid] = text_b[tid];
    vec[V_BB + tid] = bio_b[tid];
    vec[V_UA + tid] = g_uA[tid];
    vec[V_UB + tid] = g_uB[tid];
    vec[V_E  + tid] = g_e[tid];
    vec[V_CG + tid] = cls_ln_g[tid];
    vec[V_CB + tid] = cls_ln_b[tid];
    vec[V_C2 + tid]       = cls2_w[tid];
    vec[V_C2 + 256 + tid] = cls2_w[256 + tid];

    {
        __half* A2h1 = (__half*)((char*)A2h + BUF_AB);
        __half* A2l1 = (__half*)((char*)A2l + BUF_AB);
#pragma unroll
        for (int u = 0; u < 2; u++) {
            int qd = tid + u * NTHR;
            int r = qd >> 3, kq = qd & 7;
            float4 v = *(const float4*)&bio[(row0 + r) * BIO + kq * 4];
            float vv[4] = {v.x, v.y, v.z, v.w};
#pragma unroll
            for (int i = 0; i < 4; i++) {
                __half h = __float2half_rn(vv[i]);
                A2h1[r * LDT + kq * 4 + i] = h;
                A2l1[r * LDT + kq * 4 + i] = __float2half_rn(vv[i] - __half2float(h));
            }
        }
        char* Bh1 = (char*)Bh + BUF_WB;
#pragma unroll
        for (int u = 0; u < 4; u++) {
            int qd = tid + u * NTHR;
            int n = qd >> 2, c = qd & 3;
            *(uint4*)(Bh1 + n * 80 + c * 16) = *(const uint4*)((const char*)g_W1h + n * 64 + c * 16);
        }
    }
    __syncthreads();

    // prefetch W2 tile0 + text tile0 (hidden under phase-1 compute)
    WPref pw;  TPref pt;
    ldg_w(pw, g_W2h, TXT * 2, 0, tid);
    ldg_t(pt, text, row0, 0, tid);

    float acc[2][8][4];

    // ---- phase 1: bio GEMM (K=32) on buf1 ----
#pragma unroll
    for (int mt = 0; mt < 2; mt++)
#pragma unroll
        for (int nt = 0; nt < 8; nt++)
#pragma unroll
            for (int j = 0; j < 4; j++) acc[mt][nt][j] = 0.f;
    kstep2(uA2h + BUF_AB,      uA2l + BUF_AB,      aMT2, uBh + BUF_WB,      acc);
    kstep2(uA2h + BUF_AB + 32, uA2l + BUF_AB + 32, aMT2, uBh + BUF_WB + 32, acc);
    ln_writeback(acc, vec + V_BB, statS, statQ, A3h, A3l, 256, s_ab, wm, wn, lane);

    // ---- phase 2: text GEMM (K=768, 24 tiles, smem double-buffer) ----
#pragma unroll
    for (int mt = 0; mt < 2; mt++)
#pragma unroll
        for (int nt = 0; nt < 8; nt++)
#pragma unroll
            for (int j = 0; j < 4; j++) acc[mt][nt][j] = 0.f;

    for (int kt = 0; kt < 24; kt++) {
        const int wb = (kt & 1) * BUF_WB;
        const int ab = (kt & 1) * BUF_AB;
        sts_w(pw, (__half*)((char*)Bh + wb), tid);
        sts_t(pt, (__half*)((char*)A2h + ab), (__half*)((char*)A2l + ab), tid);
        __syncthreads();
        if (kt < 23) {
            ldg_w(pw, g_W2h, TXT * 2, (kt + 1) * 32, tid);
            ldg_t(pt, text, row0, (kt + 1) * 32, tid);
        } else {
            ldg_w(pw, g_W3h, 1024, 0, tid);
        }
        kstep2(uA2h + ab,      uA2l + ab,      aMT2, uBh + wb,      acc);
        kstep2(uA2h + ab + 32, uA2l + ab + 32, aMT2, uBh + wb + 32, acc);
    }
    __syncthreads();
    ln_writeback(acc, vec + V_TB, statS, statQ, A3h, A3l, 0, s_at, wm, wn, lane);

    // ---- phase 3: classifier GEMM (K=512, 16 tiles) ----
#pragma unroll
    for (int mt = 0; mt < 2; mt++)
#pragma unroll
        for (int nt = 0; nt < 8; nt++)
#pragma unroll
            for (int j = 0; j < 4; j++) acc[mt][nt][j] = 0.f;

    for (int kt = 0; kt < 16; kt++) {
        const int wb = (kt & 1) * BUF_WB;
        sts_w(pw, (__half*)((char*)Bh + wb), tid);
        __syncthreads();
        if (kt < 15) ldg_w(pw, g_W3h, 1024, (kt + 1) * 32, tid);
        unsigned a3h = uA3h + kt * 64;
        unsigned a3l = uA3l + kt * 64;
        kstep2(a3h,      a3l,      aMT3, uBh + wb,      acc);
        kstep2(a3h + 32, a3l + 32, aMT3, uBh + wb + 32, acc);
    }

    // ---- phase 4: rank-1 corrections, final LN + ReLU + head ----
    const int q = lane & 3, rq = lane >> 2;
    float at4[4], ab4[4];
#pragma unroll
    for (int i = 0; i < 4; i++) {
        int r = wm * 32 + (i >> 1) * 16 + rq + (i & 1) * 8;
        at4[i] = s_at[r];
        ab4[i] = s_ab[r];
    }
#pragma unroll
    for (int mt = 0; mt < 2; mt++)
#pragma unroll
        for (int nt = 0; nt < 8; nt++) {
            int c = wn * 64 + nt * 8 + 2 * q;
#pragma unroll
            for (int d = 0; d < 2; d++) {
                float uA = vec[V_UA + c + d];
                float uB = vec[V_UB + c + d];
                float e  = vec[V_E  + c + d];
#pragma unroll
                for (int h = 0; h < 2; h++) {
                    int i = mt * 2 + h;
                    acc[mt][nt][2 * h + d] =
                        fmaf(at4[i], uA, fmaf(ab4[i], uB, acc[mt][nt][2 * h + d] + e));
                }
            }
        }
    float s4[4], q4[4];
#pragma unroll
    for (int mt = 0; mt < 2; mt++) {
        float s0 = 0, q0 = 0, s1 = 0, q1 = 0;
#pragma unroll
        for (int nt = 0; nt < 8; nt++) {
            s0 += acc[mt][nt][0] + acc[mt][nt][1];
            s1 += acc[mt][nt][2] + acc[mt][nt][3];
            q0 = fmaf(acc[mt][nt][0], acc[mt][nt][0], fmaf(acc[mt][nt][1], acc[mt][nt][1], q0));
            q1 = fmaf(acc[mt][nt][2], acc[mt][nt][2], fmaf(acc[mt][nt][3], acc[mt][nt][3], q1));
        }
        s4[mt * 2] = s0; q4[mt * 2] = q0; s4[mt * 2 + 1] = s1; q4[mt * 2 + 1] = q1;
    }
#pragma unroll
    for (int o = 1; o <= 2; o <<= 1)
#pragma unroll
        for (int i = 0; i < 4; i++) {
            s4[i] += __shfl_xor_sync(0xffffffffu, s4[i], o);
            q4[i] += __shfl_xor_sync(0xffffffffu, q4[i], o);
        }
    __syncthreads();
    if (q == 0) {
#pragma unroll
        for (int i = 0; i < 4; i++) {
            int r = wm * 32 + (i >> 1) * 16 + rq + (i & 1) * 8;
            statS[wn * 64 + r] = s4[i];
            statQ[wn * 64 + r] = q4[i];
        }
    }
    __syncthreads();
    float mm[4], iv4[4];
#pragma unroll
    for (int i = 0; i < 4; i++) {
        int r = wm * 32 + (i >> 1) * 16 + rq + (i & 1) * 8;
        float S = statS[r] + statS[64 + r] + statS[128 + r] + statS[192 + r];
        float Q = statQ[r] + statQ[64 + r] + statQ[128 + r] + statQ[192 + r];
        mm[i]  = S * (1.f / H);
        iv4[i] = rsqrtf(fmaf(Q, 1.f / H, -mm[i] * mm[i]) + EPSLN);
    }
    float p0[4] = {0, 0, 0, 0}, p1[4] = {0, 0, 0, 0};
#pragma unroll
    for (int mt = 0; mt < 2; mt++)
#pragma unroll
        for (int nt = 0; nt < 8; nt++) {
            int c = wn * 64 + nt * 8 + 2 * q;
#pragma unroll
            for (int d = 0; d < 2; d++) {
                float cg = vec[V_CG + c + d], cb = vec[V_CB + c + d];
                float w0 = vec[V_C2 + c + d], w1 = vec[V_C2 + 256 + c + d];
#pragma unroll
                for (int h = 0; h < 2; h++) {
                    int i = mt * 2 + h;
                    float hv = fmaf((acc[mt][nt][2 * h + d] - mm[i]) * iv4[i], cg, cb);
                    hv = fmaxf(hv, 0.f);
                    p0[i] = fmaf(hv, w0, p0[i]);
                    p1[i] = fmaf(hv, w1, p1[i]);
                }
            }
        }
#pragma unroll
    for (int o = 1; o <= 2; o <<= 1)
#pragma unroll
        for (int i = 0; i < 4; i++) {
            p0[i] += __shfl_xor_sync(0xffffffffu, p0[i], o);
            p1[i] += __shfl_xor_sync(0xffffffffu, p1[i], o);
        }
    if (q == 0) {
#pragma unroll
        for (int i = 0; i < 4; i++) {
            int r = wm * 32 + (i >> 1) * 16 + rq + (i & 1) * 8;
            s_hd[wn * 128 + r * 2]     = p0[i];
            s_hd[wn * 128 + r * 2 + 1] = p1[i];
        }
    }
    __syncthreads();
    if (tid < TM) {
        int r = row0 + tid;
        out[2 * r]     = s_hd[tid * 2]     + s_hd[128 + tid * 2] +
                         s_hd[256 + tid * 2] + s_hd[384 + tid * 2] + c2b0;
        out[2 * r + 1] = s_hd[tid * 2 + 1] + s_hd[128 + tid * 2 + 1] +
                         s_hd[256 + tid * 2 + 1] + s_hd[384 + tid * 2 + 1] + c2b1;
    }
}

// ---------------- launch ----------------
extern "C" void kernel_launch(void* const* d_in, const int* in_sizes, int n_in,
                              void* d_out, int out_size) {
    const float* bio       = (const float*)d_in[0];
    const float* text      = (const float*)d_in[1];
    const float* bio_w     = (const float*)d_in[2];
    const float* bio_b     = (const float*)d_in[3];
    const float* text_w    = (const float*)d_in[4];
    const float* text_b    = (const float*)d_in[5];
    const float* ln_bio_g  = (const float*)d_in[6];
    const float* ln_bio_b  = (const float*)d_in[7];
    const float* ln_text_g = (const float*)d_in[8];
    const float* ln_text_b = (const float*)d_in[9];
    const float* in_proj_w = (const float*)d_in[10];
    const float* in_proj_b = (const float*)d_in[11];
    const float* out_w     = (const float*)d_in[12];
    const float* out_b     = (const float*)d_in[13];
    const float* cls1_w    = (const float*)d_in[14];
    const float* cls1_b    = (const float*)d_in[15];
    const float* cls_ln_g  = (const float*)d_in[16];
    const float* cls_ln_b  = (const float*)d_in[17];
    const float* cls2_w    = (const float*)d_in[18];
    const float* cls2_b    = (const float*)d_in[19];
    float* out = (float*)d_out;

    const int B = in_sizes[0] / BIO;   // 65536

    precompute1<<<H / PRC, NTHR>>>(in_proj_w, in_proj_b, out_w, out_b);
    precompute2<<<H / PRC, NTHR>>>(cls1_w, cls1_b, ln_text_g, ln_text_b, ln_bio_g, ln_bio_b);
    convert_weights<<<(H * TXT + NTHR - 1) / NTHR, NTHR>>>(bio_w, text_w);

    cudaFuncSetAttribute(fused_main, cudaFuncAttributeMaxDynamicSharedMemorySize, SMEM_BYTES);
    fused_main<<<B / TM, NTHR, SMEM_BYTES>>>(bio, text, bio_b, text_b,
                                             cls_ln_g, cls_ln_b,
                                             cls2_w, cls2_b, out);
}

// round 12
// speedup vs baseline: 6.2192x; 1.4669x over previous
#include <cuda_runtime.h>
#include <cuda_fp16.h>

#define H      256
#define TXT    768
#define BIO    32
#define TM     128
#define NTHR   256
#define EPSLN  1e-5f
#define PRC    2

#define LDA3   520      // A3 smem pitch (half elems)
#define LDT    40       // K-tile smem pitch (half elems)

// ---------------- device scratch ----------------
__device__ float g_M [H * H];
__device__ float g_c [H];
__device__ float g_Ag[H * H];
__device__ float g_Bg[H * H];
__device__ float g_uA[H];
__device__ float g_uB[H];
__device__ float g_e [H];

__device__ __align__(16) __half g_W1h[H * BIO];
__device__ __align__(16) __half g_W2h[H * TXT];
__device__ __align__(16) __half g_W3h[H * 512];

// ---------------- precompute 1 ----------------
__global__ void precompute1(const float* __restrict__ in_proj_w,
                            const float* __restrict__ in_proj_b,
                            const float* __restrict__ out_w,
                            const float* __restrict__ out_b) {
    __shared__ float s_row[PRC][H];
    __shared__ float s_part[8][PRC];
    const int i0 = blockIdx.x * PRC;
    const int j  = threadIdx.x;
    const int lane = j & 31, wrp = j >> 5;
#pragma unroll
    for (int r = 0; r < PRC; r++) s_row[r][j] = out_w[(i0 + r) * H + j];
    __syncthreads();
    float acc[PRC];
#pragma unroll
    for (int r = 0; r < PRC; r++) acc[r] = 0.f;
#pragma unroll 8
    for (int k = 0; k < H; k++) {
        float w = in_proj_w[(2 * H + k) * H + j];
#pragma unroll
        for (int r = 0; r < PRC; r++) acc[r] = fmaf(s_row[r][k], w, acc[r]);
    }
#pragma unroll
    for (int r = 0; r < PRC; r++) g_M[(i0 + r) * H + j] = acc[r];
    float bv = in_proj_b[2 * H + j];
#pragma unroll
    for (int r = 0; r < PRC; r++) {
        float v = s_row[r][j] * bv;
#pragma unroll
        for (int off = 16; off; off >>= 1) v += __shfl_xor_sync(0xffffffffu, v, off);
        if (lane == 0) s_part[wrp][r] = v;
    }
    __syncthreads();
    if (j < PRC) {
        float s = 0.f;
#pragma unroll
        for (int w = 0; w < 8; w++) s += s_part[w][j];
        g_c[i0 + j] = s + out_b[i0 + j];
    }
}

// ---------------- precompute 2 ----------------
__global__ void precompute2(const float* __restrict__ cls1_w,
                            const float* __restrict__ cls1_b,
                            const float* __restrict__ ln_text_g,
                            const float* __restrict__ ln_text_b,
                            const float* __restrict__ ln_bio_g,
                            const float* __restrict__ ln_bio_b) {
    __shared__ float s_l[PRC][H], s_r[PRC][H];
    __shared__ float s_part[8][3 * PRC];
    const int i0 = blockIdx.x * PRC;
    const int j  = threadIdx.x;
    const int lane = j & 31, wrp = j >> 5;
#pragma unroll
    for (int r = 0; r < PRC; r++) {
        s_l[r][j] = cls1_w[(i0 + r) * 2 * H + j];
        s_r[r][j] = cls1_w[(i0 + r) * 2 * H + H + j];
    }
    __syncthreads();
    float a[PRC], b[PRC];
#pragma unroll
    for (int r = 0; r < PRC; r++) { a[r] = 0.f; b[r] = 0.f; }
#pragma unroll 8
    for (int k = 0; k < H; k++) {
        float m = g_M[k * H + j];
#pragma unroll
        for (int r = 0; r < PRC; r++) {
            a[r] = fmaf(s_l[r][k], m, a[r]);
            b[r] = fmaf(s_r[r][k], m, b[r]);
        }
    }
    float gt = ln_text_g[j], gb = ln_bio_g[j];
    float lt = ln_text_b[j], lb = ln_bio_b[j];
    float cc = g_c[j];
    float vals[3 * PRC];
#pragma unroll
    for (int r = 0; r < PRC; r++) {
        float ag = a[r] * gt, bg = b[r] * gb;
        g_Ag[(i0 + r) * H + j] = ag;
        g_Bg[(i0 + r) * H + j] = bg;
        vals[r]           = ag;
        vals[PRC + r]     = bg;
        vals[2 * PRC + r] = a[r] * lt + b[r] * lb + (s_l[r][j] + s_r[r][j]) * cc;
    }
#pragma unroll
    for (int q = 0; q < 3 * PRC; q++) {
        float v = vals[q];
#pragma unroll
        for (int off = 16; off; off >>= 1) v += __shfl_xor_sync(0xffffffffu, v, off);
        if (lane == 0) s_part[wrp][q] = v;
    }
    __syncthreads();
    if (j < 3 * PRC) {
        float s = 0.f;
#pragma unroll
        for (int w = 0; w < 8; w++) s += s_part[w][j];
        int q = j / PRC, r = j % PRC;
        if (q == 0) g_uA[i0 + r] = s;
        else if (q == 1) g_uB[i0 + r] = s;
        else g_e[i0 + r] = s + cls1_b[i0 + r];
    }
}

// ---------------- precompute 3: fp16 weight casts ----------------
__global__ void convert_weights(const float* __restrict__ bio_w,
                                const float* __restrict__ text_w) {
    int i = blockIdx.x * NTHR + threadIdx.x;
    if (i < H * BIO)  g_W1h[i] = __float2half_rn(bio_w[i]);
    if (i < H * 512) {
        int n = i >> 9, k = i & 511;
        float v = (k < H) ? g_Ag[n * H + k] : g_Bg[n * H + (k - H)];
        g_W3h[i] = __float2half_rn(v);
    }
    if (i < H * TXT)  g_W2h[i] = __float2half_rn(text_w[i]);
}

// ---------------- mma helpers ----------------
__device__ __forceinline__ unsigned s2u(const void* p) {
    return (unsigned)__cvta_generic_to_shared(p);
}
__device__ __forceinline__ void ldsm4(unsigned* r, unsigned a) {
    asm volatile("ldmatrix.sync.aligned.m8n8.x4.shared.b16 {%0,%1,%2,%3}, [%4];"
                 : "=r"(r[0]), "=r"(r[1]), "=r"(r[2]), "=r"(r[3]) : "r"(a));
}
__device__ __forceinline__ void mma16816(float* d, const unsigned* a, const unsigned* b) {
    asm volatile("mma.sync.aligned.m16n8k16.row.col.f32.f16.f16.f32 "
                 "{%0,%1,%2,%3}, {%4,%5,%6,%7}, {%8,%9}, {%0,%1,%2,%3};"
                 : "+f"(d[0]), "+f"(d[1]), "+f"(d[2]), "+f"(d[3])
                 : "r"(a[0]), "r"(a[1]), "r"(a[2]), "r"(a[3]), "r"(b[0]), "r"(b[1]));
}
// one k16 step; warp tile M64xN64; single fp16 product
__device__ __forceinline__ void kstep4(unsigned aH, int aMT, unsigned bH,
                                       float (&acc)[4][8][4]) {
    unsigned ah[4][4];
#pragma unroll
    for (int mt = 0; mt < 4; mt++) ldsm4(ah[mt], aH + mt * aMT);
#pragma unroll
    for (int p = 0; p < 4; p++) {
        unsigned bh[4];
        ldsm4(bh, bH + p * (16 * LDT * 2));
#pragma unroll
        for (int mt = 0; mt < 4; mt++) {
            mma16816(acc[mt][2 * p],     ah[mt], bh);
            mma16816(acc[mt][2 * p + 1], ah[mt], bh + 2);
        }
    }
}

// ---------------- staging (register prefetch) ----------------
struct WPref { uint4 h[4]; };
__device__ __forceinline__ void ldg_w(WPref& p, const __half* srcH,
                                      int rowBytes, int k0, int tid) {
#pragma unroll
    for (int u = 0; u < 4; u++) {
        int qd = tid + u * NTHR, n = qd >> 2, c = qd & 3;
        p.h[u] = *(const uint4*)((const char*)srcH + n * rowBytes + k0 * 2 + c * 16);
    }
}
__device__ __forceinline__ void sts_w(const WPref& p, __half* Bh, int tid) {
#pragma unroll
    for (int u = 0; u < 4; u++) {
        int qd = tid + u * NTHR, n = qd >> 2, c = qd & 3;
        *(uint4*)((char*)Bh + n * 80 + c * 16) = p.h[u];
    }
}
struct TPref { float4 v[4]; };
__device__ __forceinline__ void ldg_t(TPref& p, const float* text, int row0,
                                      int k0, int tid) {
#pragma unroll
    for (int u = 0; u < 4; u++) {
        int qd = tid + u * NTHR, r = qd >> 3, kq = qd & 7;
        p.v[u] = *(const float4*)&text[(row0 + r) * TXT + k0 + kq * 4];
    }
}
__device__ __forceinline__ void sts_t(const TPref& p, __half* A2h, int tid) {
#pragma unroll
    for (int u = 0; u < 4; u++) {
        int qd = tid + u * NTHR, r = qd >> 3, kq = qd & 7;
        float vv[4] = {p.v[u].x, p.v[u].y, p.v[u].z, p.v[u].w};
#pragma unroll
        for (int i = 0; i < 4; i++)
            A2h[r * LDT + kq * 4 + i] = __float2half_rn(vv[i]);
    }
}

// ---------------- smem layout (byte offsets) ----------------
#define OFF_A3H 0            // 128 x 520 halves = 133120
#define OFF_BH  133120       // 2 bufs x 20480
#define BUF_WB  20480
#define OFF_A2H 174080       // 2 bufs x 10240
#define BUF_AB  10240
#define OFF_VEC 194560       // 2304 floats
#define OFF_SS  203776       // 512 floats
#define OFF_SQ  205824       // 512 floats
#define OFF_AT  207872       // 128 floats
#define OFF_AB2 208384       // 128 floats
#define OFF_HD  208896       // 1024 floats
#define SMEM_BYTES 212992

#define V_TB 0
#define V_BB 256
#define V_UA 512
#define V_UB 768
#define V_E  1024
#define V_CG 1280
#define V_CB 1536
#define V_C2 1792

// bias add + LN + fp16 writeback into A3 (8 stat rows per lane-quad)
__device__ __forceinline__ void ln_writeback(
    float (&acc)[4][8][4], const float* bias, float* statS, float* statQ,
    __half* A3h, int colBase, float* alpha, int wm, int wn, int lane) {
    const int q = lane & 3, rq = lane >> 2;
    const int cb0 = wn * 64 + 2 * q;
#pragma unroll
    for (int mt = 0; mt < 4; mt++)
#pragma unroll
        for (int nt = 0; nt < 8; nt++) {
            int c = cb0 + nt * 8;
            float b0 = bias[c], b1 = bias[c + 1];
            acc[mt][nt][0] += b0; acc[mt][nt][1] += b1;
            acc[mt][nt][2] += b0; acc[mt][nt][3] += b1;
        }
    float s8[8], q8[8];
#pragma unroll
    for (int mt = 0; mt < 4; mt++) {
        float s0 = 0, q0 = 0, s1 = 0, q1 = 0;
#pragma unroll
        for (int nt = 0; nt < 8; nt++) {
            s0 += acc[mt][nt][0] + acc[mt][nt][1];
            s1 += acc[mt][nt][2] + acc[mt][nt][3];
            q0 = fmaf(acc[mt][nt][0], acc[mt][nt][0], fmaf(acc[mt][nt][1], acc[mt][nt][1], q0));
            q1 = fmaf(acc[mt][nt][2], acc[mt][nt][2], fmaf(acc[mt][nt][3], acc[mt][nt][3], q1));
        }
        s8[mt * 2] = s0; q8[mt * 2] = q0; s8[mt * 2 + 1] = s1; q8[mt * 2 + 1] = q1;
    }
#pragma unroll
    for (int o = 1; o <= 2; o <<= 1)
#pragma unroll
        for (int i = 0; i < 8; i++) {
            s8[i] += __shfl_xor_sync(0xffffffffu, s8[i], o);
            q8[i] += __shfl_xor_sync(0xffffffffu, q8[i], o);
        }
    if (q == 0) {
#pragma unroll
        for (int i = 0; i < 8; i++) {
            int r = wm * 64 + (i >> 1) * 16 + rq + (i & 1) * 8;
            statS[wn * 128 + r] = s8[i];
            statQ[wn * 128 + r] = q8[i];
        }
    }
    __syncthreads();
    float inv[8];
#pragma unroll
    for (int i = 0; i < 8; i++) {
        int r = wm * 64 + (i >> 1) * 16 + rq + (i & 1) * 8;
        float S = statS[r] + statS[128 + r] + statS[256 + r] + statS[384 + r];
        float Q = statQ[r] + statQ[128 + r] + statQ[256 + r] + statQ[384 + r];
        float m = S * (1.f / H);
        float iv = rsqrtf(fmaf(Q, 1.f / H, -m * m) + EPSLN);
        inv[i] = iv;
        if (q == 0 && wn == 0) alpha[r] = -iv * m;
    }
#pragma unroll
    for (int mt = 0; mt < 4; mt++)
#pragma unroll
        for (int nt = 0; nt < 8; nt++) {
            int c = colBase + cb0 + nt * 8;
#pragma unroll
            for (int h = 0; h < 2; h++) {
                int r = wm * 64 + mt * 16 + rq + h * 8;
                float iv = inv[mt * 2 + h];
                A3h[r * LDA3 + c]     = __float2half_rn(acc[mt][nt][2 * h]     * iv);
                A3h[r * LDA3 + c + 1] = __float2half_rn(acc[mt][nt][2 * h + 1] * iv);
            }
        }
}

// ---------------- main fused kernel ----------------
__global__ __launch_bounds__(NTHR, 1)
void fused_main(const float* __restrict__ bio,
                const float* __restrict__ text,
                const float* __restrict__ bio_b,
                const float* __restrict__ text_b,
                const float* __restrict__ cls_ln_g,
                const float* __restrict__ cls_ln_b,
                const float* __restrict__ cls2_w,
                const float* __restrict__ cls2_b,
                float* __restrict__ out) {
    extern __shared__ char sm[];
    __half* A3h = (__half*)(sm + OFF_A3H);
    __half* Bh  = (__half*)(sm + OFF_BH);
    __half* A2h = (__half*)(sm + OFF_A2H);
    float* vec   = (float*)(sm + OFF_VEC);
    float* statS = (float*)(sm + OFF_SS);
    float* statQ = (float*)(sm + OFF_SQ);
    float* s_at  = (float*)(sm + OFF_AT);
    float* s_ab  = (float*)(sm + OFF_AB2);
    float* s_hd  = (float*)(sm + OFF_HD);

    const int tid  = threadIdx.x;
    const int lane = tid & 31, wid = tid >> 5;
    const int wm = wid >> 2;          // 0..1 (M64 groups)
    const int wn = wid & 3;           // 0..3 (N64 groups)
    const int row0 = blockIdx.x * TM;

    const int aRowL = lane & 15;
    const int aKoff = (lane >> 4) << 3;
    const int bNoff = ((lane >> 4) << 3) + (lane & 7);
    const int bKoff = ((lane >> 3) & 1) << 3;

    const float c2b0 = cls2_b[0];
    const float c2b1 = cls2_b[1];

    const unsigned uA3h = s2u(A3h) + ((wm * 64 + aRowL) * LDA3 + aKoff) * 2;
    const unsigned uA2h = s2u(A2h) + ((wm * 64 + aRowL) * LDT + aKoff) * 2;
    const unsigned uBh  = s2u(Bh)  + ((wn * 64 + bNoff) * LDT + bKoff) * 2;
    const int aMT2 = 16 * LDT * 2;
    const int aMT3 = 16 * LDA3 * 2;

    // ---- phase 0: vectors + bio (buf1) + W1 (buf1) ----
    vec[V_TB + tid] = text_b[tid];
    vec[V_BB + tid] = bio_b[tid];
    vec[V_UA + tid] = g_uA[tid];
    vec[V_UB + tid] = g_uB[tid];
    vec[V_E  + tid] = g_e[tid];
    vec[V_CG + tid] = cls_ln_g[tid];
    vec[V_CB + tid] = cls_ln_b[tid];
    vec[V_C2 + tid]       = cls2_w[tid];
    vec[V_C2 + 256 + tid] = cls2_w[256 + tid];

    {
        __half* A2h1 = (__half*)((char*)A2h + BUF_AB);
#pragma unroll
        for (int u = 0; u < 4; u++) {
            int qd = tid + u * NTHR;
            int r = qd >> 3, kq = qd & 7;
            float4 v = *(const float4*)&bio[(row0 + r) * BIO + kq * 4];
            float vv[4] = {v.x, v.y, v.z, v.w};
#pragma unroll
            for (int i = 0; i < 4; i++)
                A2h1[r * LDT + kq * 4 + i] = __float2half_rn(vv[i]);
        }
        char* Bh1 = (char*)Bh + BUF_WB;
#pragma unroll
        for (int u = 0; u < 4; u++) {
            int qd = tid + u * NTHR;
            int n = qd >> 2, c = qd & 3;
            *(uint4*)(Bh1 + n * 80 + c * 16) = *(const uint4*)((const char*)g_W1h + n * 64 + c * 16);
        }
    }
    __syncthreads();

    // prefetch W2 tile0 + text tile0 (hidden under phase-1 compute)
    WPref pw;  TPref pt;
    ldg_w(pw, g_W2h, TXT * 2, 0, tid);
    ldg_t(pt, text, row0, 0, tid);

    float acc[4][8][4];

    // ---- phase 1: bio GEMM (K=32) on buf1 ----
#pragma unroll
    for (int mt = 0; mt < 4; mt++)
#pragma unroll
        for (int nt = 0; nt < 8; nt++)
#pragma unroll
            for (int j = 0; j < 4; j++) acc[mt][nt][j] = 0.f;
    kstep4(uA2h + BUF_AB,      aMT2, uBh + BUF_WB,      acc);
    kstep4(uA2h + BUF_AB + 32, aMT2, uBh + BUF_WB + 32, acc);
    ln_writeback(acc, vec + V_BB, statS, statQ, A3h, 256, s_ab, wm, wn, lane);

    // ---- phase 2: text GEMM (K=768, 24 tiles, smem double-buffer) ----
#pragma unroll
    for (int mt = 0; mt < 4; mt++)
#pragma unroll
        for (int nt = 0; nt < 8; nt++)
#pragma unroll
            for (int j = 0; j < 4; j++) acc[mt][nt][j] = 0.f;

    for (int kt = 0; kt < 24; kt++) {
        const int wb = (kt & 1) * BUF_WB;
        const int ab = (kt & 1) * BUF_AB;
        sts_w(pw, (__half*)((char*)Bh + wb), tid);
        sts_t(pt, (__half*)((char*)A2h + ab), tid);
        __syncthreads();
        if (kt < 23) {
            ldg_w(pw, g_W2h, TXT * 2, (kt + 1) * 32, tid);
            ldg_t(pt, text, row0, (kt + 1) * 32, tid);
        } else {
            ldg_w(pw, g_W3h, 1024, 0, tid);
        }
        kstep4(uA2h + ab,      aMT2, uBh + wb,      acc);
        kstep4(uA2h + ab + 32, aMT2, uBh + wb + 32, acc);
    }
    __syncthreads();
    ln_writeback(acc, vec + V_TB, statS, statQ, A3h, 0, s_at, wm, wn, lane);

    // ---- phase 3: classifier GEMM (K=512, 16 tiles) ----
#pragma unroll
    for (int mt = 0; mt < 4; mt++)
#pragma unroll
        for (int nt = 0; nt < 8; nt++)
#pragma unroll
            for (int j = 0; j < 4; j++) acc[mt][nt][j] = 0.f;

    for (int kt = 0; kt < 16; kt++) {
        const int wb = (kt & 1) * BUF_WB;
        sts_w(pw, (__half*)((char*)Bh + wb), tid);
        __syncthreads();
        if (kt < 15) ldg_w(pw, g_W3h, 1024, (kt + 1) * 32, tid);
        unsigned a3h = uA3h + kt * 64;
        kstep4(a3h,      aMT3, uBh + wb,      acc);
        kstep4(a3h + 32, aMT3, uBh + wb + 32, acc);
    }

    // ---- phase 4: rank-1 corrections, final LN + ReLU + head ----
    const int q = lane & 3, rq = lane >> 2;
    float at8[8], ab8[8];
#pragma unroll
    for (int i = 0; i < 8; i++) {
        int r = wm * 64 + (i >> 1) * 16 + rq + (i & 1) * 8;
        at8[i] = s_at[r];
        ab8[i] = s_ab[r];
    }
#pragma unroll
    for (int mt = 0; mt < 4; mt++)
#pragma unroll
        for (int nt = 0; nt < 8; nt++) {
            int c = wn * 64 + nt * 8 + 2 * q;
#pragma unroll
            for (int d = 0; d < 2; d++) {
                float uA = vec[V_UA + c + d];
                float uB = vec[V_UB + c + d];
                float e  = vec[V_E  + c + d];
#pragma unroll
                for (int h = 0; h < 2; h++) {
                    int i = mt * 2 + h;
                    acc[mt][nt][2 * h + d] =
                        fmaf(at8[i], uA, fmaf(ab8[i], uB, acc[mt][nt][2 * h + d] + e));
                }
            }
        }
    float s8[8], q8[8];
#pragma unroll
    for (int mt = 0; mt < 4; mt++) {
        float s0 = 0, q0 = 0, s1 = 0, q1 = 0;
#pragma unroll
        for (int nt = 0; nt < 8; nt++) {
            s0 += acc[mt][nt][0] + acc[mt][nt][1];
            s1 += acc[mt][nt][2] + acc[mt][nt][3];
            q0 = fmaf(acc[mt][nt][0], acc[mt][nt][0], fmaf(acc[mt][nt][1], acc[mt][nt][1], q0));
            q1 = fmaf(acc[mt][nt][2], acc[mt][nt][2], fmaf(acc[mt][nt][3], acc[mt][nt][3], q1));
        }
        s8[mt * 2] = s0; q8[mt * 2] = q0; s8[mt * 2 + 1] = s1; q8[mt * 2 + 1] = q1;
    }
#pragma unroll
    for (int o = 1; o <= 2; o <<= 1)
#pragma unroll
        for (int i = 0; i < 8; i++) {
            s8[i] += __shfl_xor_sync(0xffffffffu, s8[i], o);
            q8[i] += __shfl_xor_sync(0xffffffffu, q8[i], o);
        }
    __syncthreads();
    if (q == 0) {
#pragma unroll
        for (int i = 0; i < 8; i++) {
            int r = wm * 64 + (i >> 1) * 16 + rq + (i & 1) * 8;
            statS[wn * 128 + r] = s8[i];
            statQ[wn * 128 + r] = q8[i];
        }
    }
    __syncthreads();
    float mm[8], iv8[8];
#pragma unroll
    for (int i = 0; i < 8; i++) {
        int r = wm * 64 + (i >> 1) * 16 + rq + (i & 1) * 8;
        float S = statS[r] + statS[128 + r] + statS[256 + r] + statS[384 + r];
        float Q = statQ[r] + statQ[128 + r] + statQ[256 + r] + statQ[384 + r];
        mm[i]  = S * (1.f / H);
        iv8[i] = rsqrtf(fmaf(Q, 1.f / H, -mm[i] * mm[i]) + EPSLN);
    }
    float p0[8], p1[8];
#pragma unroll
    for (int i = 0; i < 8; i++) { p0[i] = 0.f; p1[i] = 0.f; }
#pragma unroll
    for (int mt = 0; mt < 4; mt++)
#pragma unroll
        for (int nt = 0; nt < 8; nt++) {
            int c = wn * 64 + nt * 8 + 2 * q;
#pragma unroll
            for (int d = 0; d < 2; d++) {
                float cg = vec[V_CG + c + d], cb = vec[V_CB + c + d];
                float w0 = vec[V_C2 + c + d], w1 = vec[V_C2 + 256 + c + d];
#pragma unroll
                for (int h = 0; h < 2; h++) {
                    int i = mt * 2 + h;
                    float hv = fmaf((acc[mt][nt][2 * h + d] - mm[i]) * iv8[i], cg, cb);
                    hv = fmaxf(hv, 0.f);
                    p0[i] = fmaf(hv, w0, p0[i]);
                    p1[i] = fmaf(hv, w1, p1[i]);
                }
            }
        }
#pragma unroll
    for (int o = 1; o <= 2; o <<= 1)
#pragma unroll
        for (int i = 0; i < 8; i++) {
            p0[i] += __shfl_xor_sync(0xffffffffu, p0[i], o);
            p1[i] += __shfl_xor_sync(0xffffffffu, p1[i], o);
        }
    if (q == 0) {
#pragma unroll
        for (int i = 0; i < 8; i++) {
            int r = wm * 64 + (i >> 1) * 16 + rq + (i & 1) * 8;
            s_hd[wn * 256 + r * 2]     = p0[i];
            s_hd[wn * 256 + r * 2 + 1] = p1[i];
        }
    }
    __syncthreads();
    if (tid < TM) {
        int r = row0 + tid;
        out[2 * r]     = s_hd[tid * 2]       + s_hd[256 + tid * 2] +
                         s_hd[512 + tid * 2] + s_hd[768 + tid * 2] + c2b0;
        out[2 * r + 1] = s_hd[tid * 2 + 1]       + s_hd[256 + tid * 2 + 1] +
                         s_hd[512 + tid * 2 + 1] + s_hd[768 + tid * 2 + 1] + c2b1;
    }
}

// ---------------- launch ----------------
extern "C" void kernel_launch(void* const* d_in, const int* in_sizes, int n_in,
                              void* d_out, int out_size) {
    const float* bio       = (const float*)d_in[0];
    const float* text      = (const float*)d_in[1];
    const float* bio_w     = (const float*)d_in[2];
    const float* bio_b     = (const float*)d_in[3];
    const float* text_w    = (const float*)d_in[4];
    const float* text_b    = (const float*)d_in[5];
    const float* ln_bio_g  = (const float*)d_in[6];
    const float* ln_bio_b  = (const float*)d_in[7];
    const float* ln_text_g = (const float*)d_in[8];
    const float* ln_text_b = (const float*)d_in[9];
    const float* in_proj_w = (const float*)d_in[10];
    const float* in_proj_b = (const float*)d_in[11];
    const float* out_w     = (const float*)d_in[12];
    const float* out_b     = (const float*)d_in[13];
    const float* cls1_w    = (const float*)d_in[14];
    const float* cls1_b    = (const float*)d_in[15];
    const float* cls_ln_g  = (const float*)d_in[16];
    const float* cls_ln_b  = (const float*)d_in[17];
    const float* cls2_w    = (const float*)d_in[18];
    const float* cls2_b    = (const float*)d_in[19];
    float* out = (float*)d_out;

    const int B = in_sizes[0] / BIO;   // 65536

    precompute1<<<H / PRC, NTHR>>>(in_proj_w, in_proj_b, out_w, out_b);
    precompute2<<<H / PRC, NTHR>>>(cls1_w, cls1_b, ln_text_g, ln_text_b, ln_bio_g, ln_bio_b);
    convert_weights<<<(H * TXT + NTHR - 1) / NTHR, NTHR>>>(bio_w, text_w);

    cudaFuncSetAttribute(fused_main, cudaFuncAttributeMaxDynamicSharedMemorySize, SMEM_BYTES);
    fused_main<<<B / TM, NTHR, SMEM_BYTES>>>(bio, text, bio_b, text_b,
                                             cls_ln_g, cls_ln_b,
                                             cls2_w, cls2_b, out);
}